// round 2
// baseline (speedup 1.0000x reference)
#include <cuda_runtime.h>
#include <stdint.h>

#define BB 8
#define NN 8192
#define CC 64
#define NPOINT 2048
#define NSAMPLE 32
#define RADIUS2 0.04f
#define P_TOTAL (BB*NPOINT*NSAMPLE)   // 524288

#define FPS_G 8          // cluster size (CTAs per batch)
#define FPS_T 256        // threads per FPS CTA -> 4 points/thread

// ---------------- scratch (device globals; no allocation allowed) ------------
__device__ float d_featT[BB*NN*CC];                 // 16.8 MB  (B,N,C)
__device__ int   d_ball_idx[P_TOTAL];
__device__ float d_h1[(size_t)64*P_TOTAL];          // 134 MB
__device__ float d_h2[(size_t)64*P_TOTAL];          // 134 MB
__device__ float d_hmx[(size_t)128*BB*NPOINT];      // 8 MB
__device__ float d_hmn[(size_t)128*BB*NPOINT];      // 8 MB
__device__ float d_partials[4096*128*2];            // 4 MB
__device__ float d_ab[128*2];                       // fused BN scale/shift

// ---------------- packed f32x2 helpers (exact per-element RN) ----------------
#define PACK2(out, lo, hi)  asm("mov.b64 %0, {%1, %2};" : "=l"(out) : "f"(lo), "f"(hi))
#define UNPACK2(lo, hi, in) asm("mov.b64 {%0, %1}, %2;" : "=f"(lo), "=f"(hi) : "l"(in))
#define ADD2(out, a, b)     asm("add.rn.f32x2 %0, %1, %2;" : "=l"(out) : "l"(a), "l"(b))
#define MUL2(out, a, b)     asm("mul.rn.f32x2 %0, %1, %2;" : "=l"(out) : "l"(a), "l"(b))

__device__ __forceinline__ uint32_t smem_u32(const void* p) {
    uint32_t a;
    asm("{ .reg .u64 t; cvta.to.shared.u64 t, %1; cvt.u32.u64 %0, t; }" : "=r"(a) : "l"(p));
    return a;
}

// ---------------- feature transpose (B,C,N) -> (B,N,C) -----------------------
__global__ void k_transpose(const float* __restrict__ f) {
    __shared__ float tile[32][33];
    int b = blockIdx.z, n0 = blockIdx.x*32, c0 = blockIdx.y*32;
    int tx = threadIdx.x, ty = threadIdx.y;
    for (int i = ty; i < 32; i += 8)
        tile[i][tx] = f[((size_t)b*CC + c0 + i)*NN + n0 + tx];
    __syncthreads();
    for (int i = ty; i < 32; i += 8)
        d_featT[((size_t)b*NN + n0 + i)*CC + c0 + tx] = tile[tx][i];
}

// ---------------- furthest point sampling: cluster of 8 CTAs per batch -------
// Each CTA owns 1024 contiguous points (4 per thread). Per iteration:
//  local best -> warp REDUX -> CTA reduce -> broadcast (key,coords) to all 8
//  peers via st.shared::cluster + mbarrier.arrive.release.cluster; everyone
//  waits its local mbarrier (8 arrivals) and redundantly reduces 8 slots.
__global__ __cluster_dims__(FPS_G,1,1) __launch_bounds__(FPS_T,1)
void k_fps(const float* __restrict__ xyz, float* __restrict__ out_newxyz) {
    const int tid = threadIdx.x;
    const int lane = tid & 31;
    const int w = tid >> 5;                    // 8 warps
    uint32_t rank; asm("mov.u32 %0, %%cluster_ctarank;" : "=r"(rank));
    const int b = blockIdx.x / FPS_G;
    const float* xb = xyz + (size_t)b*NN*3;

    // register-resident points: 4 per thread, packed as f32x2 pairs
    const int base = (int)rank*1024 + tid*4;
    float x0=xb[(base+0)*3+0], y0=xb[(base+0)*3+1], z0=xb[(base+0)*3+2];
    float x1=xb[(base+1)*3+0], y1=xb[(base+1)*3+1], z1=xb[(base+1)*3+2];
    float x2=xb[(base+2)*3+0], y2=xb[(base+2)*3+1], z2=xb[(base+2)*3+2];
    float x3=xb[(base+3)*3+0], y3=xb[(base+3)*3+1], z3=xb[(base+3)*3+2];
    unsigned long long X01,Y01,Z01,X23,Y23,Z23;
    PACK2(X01,x0,x1); PACK2(Y01,y0,y1); PACK2(Z01,z0,z1);
    PACK2(X23,x2,x3); PACK2(Y23,y2,y3); PACK2(Z23,z2,z3);
    float dd0=1e10f, dd1=1e10f, dd2=1e10f, dd3=1e10f;

    __shared__ unsigned long long s_wkey[8];
    __shared__ float s_wx[8], s_wy[8], s_wz[8];
    __shared__ unsigned long long c_key[2][FPS_G];
    __shared__ unsigned long long c_xy[2][FPS_G];
    __shared__ float c_z[2][FPS_G];
    __shared__ alignas(8) unsigned long long s_mbar;

    uint32_t mbar_a = smem_u32(&s_mbar);
    if (tid == 0)
        asm volatile("mbarrier.init.shared.b64 [%0], %1;" :: "r"(mbar_a), "r"(FPS_G) : "memory");
    __syncthreads();
    // cluster barrier: all mbarriers initialized before any remote traffic
    asm volatile("barrier.cluster.arrive.aligned;" ::: "memory");
    asm volatile("barrier.cluster.wait.aligned;"   ::: "memory");

    // iteration 0: point 0
    float lx = xb[0], ly = xb[1], lz = xb[2];
    if (rank == 0 && tid == 0) {
        float* o = out_newxyz + (size_t)b*NPOINT*3;
        o[0] = lx; o[1] = ly; o[2] = lz;
    }

    for (int it = 1; it < NPOINT; it++) {
        const int par = (it-1) & 1;
        // negated last point, packed (a + (-b) == a - b exactly)
        float nlx = -lx, nly = -ly, nlz = -lz;
        unsigned long long NL_X, NL_Y, NL_Z;
        PACK2(NL_X,nlx,nlx); PACK2(NL_Y,nly,nly); PACK2(NL_Z,nlz,nlz);

        unsigned long long dx,dy,dz,sx,sy,sz,s01,s23,t;
        float da, db2;
        // pair (0,1)
        ADD2(dx,X01,NL_X); ADD2(dy,Y01,NL_Y); ADD2(dz,Z01,NL_Z);
        MUL2(sx,dx,dx); MUL2(sy,dy,dy); MUL2(sz,dz,dz);
        ADD2(t,sx,sy); ADD2(s01,t,sz);
        UNPACK2(da,db2,s01);
        dd0 = fminf(dd0,da); dd1 = fminf(dd1,db2);
        // pair (2,3)
        ADD2(dx,X23,NL_X); ADD2(dy,Y23,NL_Y); ADD2(dz,Z23,NL_Z);
        MUL2(sx,dx,dx); MUL2(sy,dy,dy); MUL2(sz,dz,dz);
        ADD2(t,sx,sy); ADD2(s23,t,sz);
        UNPACK2(da,db2,s23);
        dd2 = fminf(dd2,da); dd3 = fminf(dd3,db2);

        float bv = fmaxf(fmaxf(dd0,dd1), fmaxf(dd2,dd3));
        unsigned vb = __float_as_uint(bv);                 // >=0: monotone bits
        unsigned wmax = __reduce_max_sync(0xffffffffu, vb);
        unsigned cand = 0xffffffffu;
        if (__float_as_uint(dd0)==wmax) cand = (unsigned)(base+0);
        if (__float_as_uint(dd1)==wmax) cand = min(cand,(unsigned)(base+1));
        if (__float_as_uint(dd2)==wmax) cand = min(cand,(unsigned)(base+2));
        if (__float_as_uint(dd3)==wmax) cand = min(cand,(unsigned)(base+3));
        unsigned widx = __reduce_min_sync(0xffffffffu, cand);
        if (lane == 0)
            s_wkey[w] = ((unsigned long long)wmax << 32) | (0xffffffffu - widx);
        if (cand == widx) {            // unique owner lane supplies coords
            float ox = (widx==(unsigned)(base+0)) ? x0 : (widx==(unsigned)(base+1)) ? x1
                     : (widx==(unsigned)(base+2)) ? x2 : x3;
            float oy = (widx==(unsigned)(base+0)) ? y0 : (widx==(unsigned)(base+1)) ? y1
                     : (widx==(unsigned)(base+2)) ? y2 : y3;
            float oz = (widx==(unsigned)(base+0)) ? z0 : (widx==(unsigned)(base+1)) ? z1
                     : (widx==(unsigned)(base+2)) ? z2 : z3;
            s_wx[w]=ox; s_wy[w]=oy; s_wz[w]=oz;
        }
        __syncthreads();

        if (tid == 0) {
            unsigned long long bk = s_wkey[0];
            int bw = 0;
#pragma unroll
            for (int j = 1; j < 8; j++)
                if (s_wkey[j] > bk) { bk = s_wkey[j]; bw = j; }
            float bx = s_wx[bw], by = s_wy[bw], bz = s_wz[bw];
            unsigned long long bxy; PACK2(bxy,bx,by);
            uint32_t a_key = smem_u32(&c_key[par][rank]);
            uint32_t a_xy  = smem_u32(&c_xy[par][rank]);
            uint32_t a_z   = smem_u32(&c_z[par][rank]);
#pragma unroll
            for (int p = 0; p < FPS_G; p++) {
                asm volatile(
                    "{ .reg .b32 r1, r2, r3, r4;\n\t"
                    "mapa.shared::cluster.u32 r1, %0, %4;\n\t"
                    "mapa.shared::cluster.u32 r2, %1, %4;\n\t"
                    "mapa.shared::cluster.u32 r3, %2, %4;\n\t"
                    "mapa.shared::cluster.u32 r4, %3, %4;\n\t"
                    "st.shared::cluster.b64 [r1], %5;\n\t"
                    "st.shared::cluster.b64 [r2], %6;\n\t"
                    "st.shared::cluster.b32 [r3], %7;\n\t"
                    "mbarrier.arrive.release.cluster.shared::cluster.b64 _, [r4];\n\t"
                    "}"
                    :: "r"(a_key), "r"(a_xy), "r"(a_z), "r"(mbar_a), "r"(p),
                       "l"(bk), "l"(bxy), "f"(bz)
                    : "memory");
            }
        }
        // wait: 8 arrivals, phase = (it-1)&1
        {
            uint32_t ph = (uint32_t)par;
            uint32_t done;
            asm volatile(
                "{ .reg .pred p;\n\t"
                "mbarrier.try_wait.parity.acquire.cluster.shared::cta.b64 p, [%1], %2;\n\t"
                "selp.b32 %0, 1, 0, p; }"
                : "=r"(done) : "r"(mbar_a), "r"(ph) : "memory");
            if (!done) {
                asm volatile(
                    "{ .reg .pred P1;\n\t"
                    "WL_%=:\n\t"
                    "mbarrier.try_wait.parity.acquire.cluster.shared::cta.b64 P1, [%0], %1, 0x989680;\n\t"
                    "@P1 bra.uni WD_%=;\n\t"
                    "bra.uni WL_%=;\n\t"
                    "WD_%=:\n\t}"
                    :: "r"(mbar_a), "r"(ph) : "memory");
            }
        }
        // global winner from local slots
        unsigned long long gk = c_key[par][0]; int gw = 0;
#pragma unroll
        for (int j = 1; j < FPS_G; j++)
            if (c_key[par][j] > gk) { gk = c_key[par][j]; gw = j; }
        float wx2, wy2;
        UNPACK2(wx2, wy2, c_xy[par][gw]);
        lx = wx2; ly = wy2; lz = c_z[par][gw];
        if (rank == 0 && tid == 0) {
            float* o = out_newxyz + ((size_t)b*NPOINT + it)*3;
            o[0] = lx; o[1] = ly; o[2] = lz;
        }
    }
    asm volatile("barrier.cluster.arrive.aligned;" ::: "memory");
    asm volatile("barrier.cluster.wait.aligned;"   ::: "memory");
}

// ---------------- ball query: warp per (b,s), first-32 in index order --------
__global__ void k_ballquery(const float* __restrict__ xyz,
                            const float* __restrict__ newxyz) {
    int warp = (blockIdx.x*blockDim.x + threadIdx.x) >> 5;
    int lane = threadIdx.x & 31;
    if (warp >= BB*NPOINT) return;
    int b = warp / NPOINT;
    const float* xb = xyz + (size_t)b*NN*3;
    const float* np = newxyz + (size_t)warp*3;
    float qx = np[0], qy = np[1], qz = np[2];
    int* outp = d_ball_idx + (size_t)warp*NSAMPLE;

    int cnt = 0, firstIdx = 0; bool haveFirst = false;
    for (int j0 = 0; j0 < NN && cnt < NSAMPLE; j0 += 32) {
        int j = j0 + lane;
        float dx = __fadd_rn(xb[j*3+0], -qx);
        float dy = __fadd_rn(xb[j*3+1], -qy);
        float dz = __fadd_rn(xb[j*3+2], -qz);
        float d = __fadd_rn(__fadd_rn(__fmul_rn(dx,dx), __fmul_rn(dy,dy)),
                            __fmul_rn(dz,dz));
        bool in = d < RADIUS2;
        unsigned m = __ballot_sync(0xffffffffu, in);
        if (m) {
            if (!haveFirst) { firstIdx = j0 + __ffs(m) - 1; haveFirst = true; }
            if (in) {
                int pos = cnt + __popc(m & ((1u << lane) - 1u));
                if (pos < NSAMPLE) outp[pos] = j;
            }
            cnt += __popc(m);
        }
    }
    int fs = cnt < NSAMPLE ? cnt : NSAMPLE;
    for (int pos = fs + lane; pos < NSAMPLE; pos += 32) outp[pos] = firstIdx;
}

// ---------------- layer 1: gather + GEMM(64x67) + stat partials --------------
__global__ __launch_bounds__(256,2) void k_layer1(const float* __restrict__ xyz,
                                                  const float* __restrict__ newxyz,
                                                  const float* __restrict__ W1) {
    extern __shared__ float sm[];
    float (*sg)[256] = (float(*)[256])sm;              // 67 x 256
    float (*sw)[64]  = (float(*)[64])(sm + 67*256);    // 67 x 64
    int tid = threadIdx.x;
    int pos0 = blockIdx.x * 256;

    for (int i = tid; i < 64*67; i += 256) { int o = i/67, c = i%67; sw[c][o] = W1[i]; }
    {   // gather one position per thread
        int pos = pos0 + tid;
        int idx = d_ball_idx[pos];
        int b = pos >> 16;
        int s = (pos >> 5) & 2047;
        const float* nx = newxyz + ((size_t)b*NPOINT + s)*3;
        const float* pp = xyz + ((size_t)b*NN + idx)*3;
        sg[0][tid] = pp[0]-nx[0];
        sg[1][tid] = pp[1]-nx[1];
        sg[2][tid] = pp[2]-nx[2];
        const float4* fr = (const float4*)(d_featT + ((size_t)b*NN + idx)*CC);
#pragma unroll
        for (int c4 = 0; c4 < 16; c4++) {
            float4 v = fr[c4];
            sg[3+c4*4+0][tid] = v.x; sg[3+c4*4+1][tid] = v.y;
            sg[3+c4*4+2][tid] = v.z; sg[3+c4*4+3][tid] = v.w;
        }
    }
    __syncthreads();

    int tr = tid >> 5, tc = tid & 31;
    float acc[8][8];
#pragma unroll
    for (int i=0;i<8;i++)
#pragma unroll
        for (int j=0;j<8;j++) acc[i][j]=0.f;

#pragma unroll 2
    for (int k = 0; k < 67; k++) {
        float wv[8], g[8];
        *(float4*)&wv[0] = *(const float4*)&sw[k][tr*8];
        *(float4*)&wv[4] = *(const float4*)&sw[k][tr*8+4];
        *(float4*)&g[0] = *(const float4*)&sg[k][tc*8];
        *(float4*)&g[4] = *(const float4*)&sg[k][tc*8+4];
#pragma unroll
        for (int i=0;i<8;i++)
#pragma unroll
            for (int j=0;j<8;j++) acc[i][j] += wv[i]*g[j];
    }
#pragma unroll
    for (int i = 0; i < 8; i++) {
        int c = tr*8 + i;
        float* hp = d_h1 + (size_t)c*P_TOTAL + pos0 + tc*8;
        *(float4*)hp     = make_float4(acc[i][0],acc[i][1],acc[i][2],acc[i][3]);
        *(float4*)(hp+4) = make_float4(acc[i][4],acc[i][5],acc[i][6],acc[i][7]);
    }
#pragma unroll
    for (int i = 0; i < 8; i++) {
        float s = 0.f, q = 0.f;
#pragma unroll
        for (int j = 0; j < 8; j++) { s += acc[i][j]; q += acc[i][j]*acc[i][j]; }
#pragma unroll
        for (int o = 16; o > 0; o >>= 1) {
            s += __shfl_xor_sync(0xffffffffu, s, o);
            q += __shfl_xor_sync(0xffffffffu, q, o);
        }
        if (tc == 0) {
            int c = tr*8 + i;
            d_partials[((size_t)blockIdx.x*128 + c)*2 + 0] = s;
            d_partials[((size_t)blockIdx.x*128 + c)*2 + 1] = q;
        }
    }
}

// ---------------- deterministic stats reduce + BN fold -----------------------
__global__ void k_stats(const float* __restrict__ gam, const float* __restrict__ bet,
                        int nblocks) {
    int c = blockIdx.x, t = threadIdx.x;
    double s = 0.0, q = 0.0;
    for (int i = t; i < nblocks; i += 256) {
        s += (double)d_partials[((size_t)i*128 + c)*2 + 0];
        q += (double)d_partials[((size_t)i*128 + c)*2 + 1];
    }
    __shared__ double ss[256], qq[256];
    ss[t] = s; qq[t] = q; __syncthreads();
    for (int o = 128; o > 0; o >>= 1) {
        if (t < o) { ss[t] += ss[t+o]; qq[t] += qq[t+o]; }
        __syncthreads();
    }
    if (t == 0) {
        double mu  = ss[0] / (double)P_TOTAL;
        double var = qq[0] / (double)P_TOTAL - mu*mu;
        float a  = (float)((double)gam[c] / sqrt(var + 1e-5));
        float bp = (float)((double)bet[c] - mu * (double)a);
        d_ab[c*2] = a; d_ab[c*2+1] = bp;
    }
}

// ---------------- layer 2: bn1+relu on load, GEMM(64x64) ---------------------
__global__ __launch_bounds__(256,2) void k_layer2(const float* __restrict__ W2) {
    extern __shared__ float sm[];
    float (*sg)[256] = (float(*)[256])sm;              // 64 x 256
    float (*sw)[64]  = (float(*)[64])(sm + 64*256);    // 64 x 64
    int tid = threadIdx.x;
    int pos0 = blockIdx.x * 256;
    int wid = tid >> 5, lane = tid & 31;

    for (int i = tid; i < 64*64; i += 256) { int o = i/64, c = i%64; sw[c][o] = W2[i]; }
    for (int c = wid; c < 64; c += 8) {
        float a = d_ab[c*2], bp = d_ab[c*2+1];
        const float4* src = (const float4*)(d_h1 + (size_t)c*P_TOTAL + pos0) + lane*2;
        float4 v0 = src[0], v1 = src[1];
        v0.x=fmaxf(0.f,a*v0.x+bp); v0.y=fmaxf(0.f,a*v0.y+bp);
        v0.z=fmaxf(0.f,a*v0.z+bp); v0.w=fmaxf(0.f,a*v0.w+bp);
        v1.x=fmaxf(0.f,a*v1.x+bp); v1.y=fmaxf(0.f,a*v1.y+bp);
        v1.z=fmaxf(0.f,a*v1.z+bp); v1.w=fmaxf(0.f,a*v1.w+bp);
        *(float4*)&sg[c][lane*8]   = v0;
        *(float4*)&sg[c][lane*8+4] = v1;
    }
    __syncthreads();

    int tr = wid, tc = lane;
    float acc[8][8];
#pragma unroll
    for (int i=0;i<8;i++)
#pragma unroll
        for (int j=0;j<8;j++) acc[i][j]=0.f;
#pragma unroll 2
    for (int k = 0; k < 64; k++) {
        float wv[8], g[8];
        *(float4*)&wv[0] = *(const float4*)&sw[k][tr*8];
        *(float4*)&wv[4] = *(const float4*)&sw[k][tr*8+4];
        *(float4*)&g[0] = *(const float4*)&sg[k][tc*8];
        *(float4*)&g[4] = *(const float4*)&sg[k][tc*8+4];
#pragma unroll
        for (int i=0;i<8;i++)
#pragma unroll
            for (int j=0;j<8;j++) acc[i][j] += wv[i]*g[j];
    }
#pragma unroll
    for (int i = 0; i < 8; i++) {
        int c = tr*8 + i;
        float* hp = d_h2 + (size_t)c*P_TOTAL + pos0 + tc*8;
        *(float4*)hp     = make_float4(acc[i][0],acc[i][1],acc[i][2],acc[i][3]);
        *(float4*)(hp+4) = make_float4(acc[i][4],acc[i][5],acc[i][6],acc[i][7]);
    }
#pragma unroll
    for (int i = 0; i < 8; i++) {
        float s = 0.f, q = 0.f;
#pragma unroll
        for (int j = 0; j < 8; j++) { s += acc[i][j]; q += acc[i][j]*acc[i][j]; }
#pragma unroll
        for (int o = 16; o > 0; o >>= 1) {
            s += __shfl_xor_sync(0xffffffffu, s, o);
            q += __shfl_xor_sync(0xffffffffu, q, o);
        }
        if (tc == 0) {
            int c = tr*8 + i;
            d_partials[((size_t)blockIdx.x*128 + c)*2 + 0] = s;
            d_partials[((size_t)blockIdx.x*128 + c)*2 + 1] = q;
        }
    }
}

// ---------------- layer 3: bn2+relu on load, GEMM(128x64), fused max/min -----
// tile: 128 out x 128 pos, 256 threads (tr=tid/16, tc=tid%16), 8x8 each.
// Writes per-(c, b, s) max/min of h3 over the 32-sample window instead of h3.
__global__ __launch_bounds__(256,2) void k_layer3(const float* __restrict__ W3) {
    extern __shared__ float sm[];
    float (*sg)[128] = (float(*)[128])sm;              // 64 x 128
    float (*sw)[128] = (float(*)[128])(sm + 64*128);   // 64 x 128
    int tid = threadIdx.x;
    int pos0 = blockIdx.x * 128;
    int wid = tid >> 5, lane = tid & 31;

    for (int i = tid; i < 128*64; i += 256) { int o = i/64, c = i%64; sw[c][o] = W3[i]; }
    for (int c = wid; c < 64; c += 8) {
        float a = d_ab[c*2], bp = d_ab[c*2+1];
        const float4* src = (const float4*)(d_h2 + (size_t)c*P_TOTAL + pos0);
        float4 v = src[lane];
        v.x=fmaxf(0.f,a*v.x+bp); v.y=fmaxf(0.f,a*v.y+bp);
        v.z=fmaxf(0.f,a*v.z+bp); v.w=fmaxf(0.f,a*v.w+bp);
        *(float4*)&sg[c][lane*4] = v;
    }
    __syncthreads();

    int tr = tid >> 4, tc = tid & 15;
    float acc[8][8];
#pragma unroll
    for (int i=0;i<8;i++)
#pragma unroll
        for (int j=0;j<8;j++) acc[i][j]=0.f;
#pragma unroll 2
    for (int k = 0; k < 64; k++) {
        float wv[8], g[8];
        *(float4*)&wv[0] = *(const float4*)&sw[k][tr*8];
        *(float4*)&wv[4] = *(const float4*)&sw[k][tr*8+4];
        *(float4*)&g[0] = *(const float4*)&sg[k][tc*8];
        *(float4*)&g[4] = *(const float4*)&sg[k][tc*8+4];
#pragma unroll
        for (int i=0;i<8;i++)
#pragma unroll
            for (int j=0;j<8;j++) acc[i][j] += wv[i]*g[j];
    }
    // fused max/min over 32-sample window: 4 threads (tc within group of 4)
    // hold the 32 samples of one (b,s) group.
    int sglob = (pos0 >> 5) + (tc >> 2);   // flattened b*NPOINT + s
#pragma unroll
    for (int i = 0; i < 8; i++) {
        int c = tr*8 + i;
        float mx = acc[i][0], mn = acc[i][0];
#pragma unroll
        for (int j = 1; j < 8; j++) { mx = fmaxf(mx, acc[i][j]); mn = fminf(mn, acc[i][j]); }
        mx = fmaxf(mx, __shfl_xor_sync(0xffffffffu, mx, 1));
        mn = fminf(mn, __shfl_xor_sync(0xffffffffu, mn, 1));
        mx = fmaxf(mx, __shfl_xor_sync(0xffffffffu, mx, 2));
        mn = fminf(mn, __shfl_xor_sync(0xffffffffu, mn, 2));
        if ((tc & 3) == 0) {
            d_hmx[(size_t)c*(BB*NPOINT) + sglob] = mx;
            d_hmn[(size_t)c*(BB*NPOINT) + sglob] = mn;
        }
    }
    // stat partials
#pragma unroll
    for (int i = 0; i < 8; i++) {
        float s = 0.f, q = 0.f;
#pragma unroll
        for (int j = 0; j < 8; j++) { s += acc[i][j]; q += acc[i][j]*acc[i][j]; }
#pragma unroll
        for (int o = 8; o > 0; o >>= 1) {
            s += __shfl_xor_sync(0xffffffffu, s, o);
            q += __shfl_xor_sync(0xffffffffu, q, o);
        }
        if (tc == 0) {
            int c = tr*8 + i;
            d_partials[((size_t)blockIdx.x*128 + c)*2 + 0] = s;
            d_partials[((size_t)blockIdx.x*128 + c)*2 + 1] = q;
        }
    }
}

// ---------------- bn3 + relu on the pooled extremum --------------------------
__global__ void k_finalize(float* __restrict__ feats) {
    int gid = blockIdx.x*blockDim.x + threadIdx.x;   // b*128*2048 + o*2048 + s
    if (gid >= BB*128*NPOINT) return;
    int s = gid & 2047;
    int o = (gid >> 11) & 127;
    int b = gid >> 18;
    float a = d_ab[o*2], bp = d_ab[o*2+1];
    size_t ix = (size_t)o*(BB*NPOINT) + b*NPOINT + s;
    float v = (a >= 0.0f) ? d_hmx[ix] : d_hmn[ix];
    feats[gid] = fmaxf(0.0f, a*v + bp);
}

// ---------------- launch ------------------------------------------------------
extern "C" void kernel_launch(void* const* d_in, const int* in_sizes, int n_in,
                              void* d_out, int out_size) {
    const float* xyz      = (const float*)d_in[0];
    const float* features = (const float*)d_in[1];
    const float* W1 = (const float*)d_in[2];
    const float* g1 = (const float*)d_in[3];
    const float* b1 = (const float*)d_in[4];
    const float* W2 = (const float*)d_in[5];
    const float* g2 = (const float*)d_in[6];
    const float* b2 = (const float*)d_in[7];
    const float* W3 = (const float*)d_in[8];
    const float* g3 = (const float*)d_in[9];
    const float* b3 = (const float*)d_in[10];
    float* out    = (float*)d_out;
    float* newxyz = out;                       // 8*2048*3
    float* feats  = out + BB*NPOINT*3;         // 8*128*2048

    const int SM1 = (67*256 + 67*64) * 4;      // 85760
    const int SM2 = (64*256 + 64*64) * 4;      // 81920
    const int SM3 = (64*128 + 64*128) * 4;     // 65536
    cudaFuncSetAttribute(k_layer1, cudaFuncAttributeMaxDynamicSharedMemorySize, SM1);
    cudaFuncSetAttribute(k_layer2, cudaFuncAttributeMaxDynamicSharedMemorySize, SM2);
    cudaFuncSetAttribute(k_layer3, cudaFuncAttributeMaxDynamicSharedMemorySize, SM3);

    k_transpose<<<dim3(NN/32, CC/32, BB), dim3(32,8)>>>(features);
    k_fps<<<BB*FPS_G, FPS_T>>>(xyz, newxyz);
    k_ballquery<<<(BB*NPOINT)/4, 128>>>(xyz, newxyz);

    k_layer1<<<P_TOTAL/256, 256, SM1>>>(xyz, newxyz, W1);
    k_stats<<<64, 256>>>(g1, b1, P_TOTAL/256);
    k_layer2<<<P_TOTAL/256, 256, SM2>>>(W2);
    k_stats<<<64, 256>>>(g2, b2, P_TOTAL/256);
    k_layer3<<<P_TOTAL/128, 256, SM3>>>(W3);
    k_stats<<<128, 256>>>(g3, b3, P_TOTAL/128);
    k_finalize<<<(BB*128*NPOINT)/256, 256>>>(feats);
}

// round 3
// speedup vs baseline: 2.3667x; 2.3667x over previous
#include <cuda_runtime.h>
#include <stdint.h>

#define BB 8
#define NN 8192
#define CC 64
#define NPOINT 2048
#define NSAMPLE 32
#define RADIUS2 0.04f
#define P_TOTAL (BB*NPOINT*NSAMPLE)   // 524288

// ---------------- scratch (device globals; no allocation allowed) ------------
__device__ float d_featT[BB*NN*CC];                 // 16.8 MB  (B,N,C)
__device__ int   d_ball_idx[P_TOTAL];
__device__ float d_h1[(size_t)64*P_TOTAL];          // 134 MB
__device__ float d_h2[(size_t)64*P_TOTAL];          // 134 MB
__device__ float d_hmx[(size_t)128*BB*NPOINT];      // 8 MB
__device__ float d_hmn[(size_t)128*BB*NPOINT];      // 8 MB
__device__ float d_partials[4096*128*2];            // 4 MB
__device__ float d_ab[128*2];                       // fused BN scale/shift
// Morton-sorted copies of xyz (+ original index)
__device__ float d_sx[BB*NN], d_sy[BB*NN], d_sz[BB*NN];
__device__ int   d_sidx[BB*NN];

// ---------------- packed f32x2 helpers (exact per-element RN) ----------------
#define PACK2(out, lo, hi)  asm("mov.b64 %0, {%1, %2};" : "=l"(out) : "f"(lo), "f"(hi))
#define UNPACK2(lo, hi, in) asm("mov.b64 {%0, %1}, %2;" : "=f"(lo), "=f"(hi) : "l"(in))
#define ADD2(out, a, b)     asm("add.rn.f32x2 %0, %1, %2;" : "=l"(out) : "l"(a), "l"(b))
#define MUL2(out, a, b)     asm("mul.rn.f32x2 %0, %1, %2;" : "=l"(out) : "l"(a), "l"(b))

// ---------------- feature transpose (B,C,N) -> (B,N,C) -----------------------
__global__ void k_transpose(const float* __restrict__ f) {
    __shared__ float tile[32][33];
    int b = blockIdx.z, n0 = blockIdx.x*32, c0 = blockIdx.y*32;
    int tx = threadIdx.x, ty = threadIdx.y;
    for (int i = ty; i < 32; i += 8)
        tile[i][tx] = f[((size_t)b*CC + c0 + i)*NN + n0 + tx];
    __syncthreads();
    for (int i = ty; i < 32; i += 8)
        d_featT[((size_t)b*NN + n0 + i)*CC + c0 + tx] = tile[tx][i];
}

// ---------------- Morton counting sort: one CTA per batch --------------------
__global__ __launch_bounds__(1024,1) void k_sort(const float* __restrict__ xyz) {
    __shared__ int cnt[4096];
    __shared__ unsigned short cell[8192];
    __shared__ int wsum[32];
    int b = blockIdx.x, t = threadIdx.x;
    for (int i = t; i < 4096; i += 1024) cnt[i] = 0;
    __syncthreads();
    const float* xb = xyz + (size_t)b*NN*3;
    for (int i = t; i < NN; i += 1024) {
        float x = xb[i*3+0], y = xb[i*3+1], z = xb[i*3+2];
        int cx = min(15, max(0, (int)(x*16.0f)));
        int cy = min(15, max(0, (int)(y*16.0f)));
        int cz = min(15, max(0, (int)(z*16.0f)));
        int m = 0;
#pragma unroll
        for (int j = 0; j < 4; j++)
            m |= (((cx>>j)&1)<<(3*j)) | (((cy>>j)&1)<<(3*j+1)) | (((cz>>j)&1)<<(3*j+2));
        cell[i] = (unsigned short)m;
        atomicAdd(&cnt[m], 1);
    }
    __syncthreads();
    // exclusive prefix sum over 4096 cells (4 per thread)
    int c0 = cnt[t*4+0], c1 = cnt[t*4+1], c2 = cnt[t*4+2], c3 = cnt[t*4+3];
    int ts = c0+c1+c2+c3;
    int lane = t & 31, w = t >> 5;
    int x = ts;
#pragma unroll
    for (int o = 1; o < 32; o <<= 1) {
        int y = __shfl_up_sync(0xffffffffu, x, o);
        if (lane >= o) x += y;
    }
    if (lane == 31) wsum[w] = x;
    int wex = x - ts;
    __syncthreads();
    if (w == 0) {
        int v = wsum[lane];
        int xx = v;
#pragma unroll
        for (int o = 1; o < 32; o <<= 1) {
            int y = __shfl_up_sync(0xffffffffu, xx, o);
            if (lane >= o) xx += y;
        }
        wsum[lane] = xx - v;
    }
    __syncthreads();
    int basep = wsum[w] + wex;
    cnt[t*4+0] = basep;
    cnt[t*4+1] = basep + c0;
    cnt[t*4+2] = basep + c0 + c1;
    cnt[t*4+3] = basep + c0 + c1 + c2;
    __syncthreads();
    // scatter
    for (int i = t; i < NN; i += 1024) {
        int m = cell[i];
        int pos = atomicAdd(&cnt[m], 1);
        d_sx[b*NN+pos] = xb[i*3+0];
        d_sy[b*NN+pos] = xb[i*3+1];
        d_sz[b*NN+pos] = xb[i*3+2];
        d_sidx[b*NN+pos] = i;
    }
}

// ---------------- FPS: 1 CTA/batch, 512 thr, pruned + f32x2 ------------------
// Thread owns 16 CONSECUTIVE Morton-sorted points (registers). Warp = 512
// compact points with a bounding box; per iteration the warp skips its whole
// update iff dist2(center, box)*(1-1e-4) >= max(dd in warp) — a provable
// bitwise no-op (min(dd,d)=dd for all its points).
__global__ __launch_bounds__(512,1) void k_fps(const float* __restrict__ xyz,
                                               float* __restrict__ out_newxyz) {
    extern __shared__ float smem[];
    float* s_px = smem;             // 8192
    float* s_py = smem + 8192;
    float* s_pz = smem + 16384;
    __shared__ unsigned long long s_wkey[16];
    __shared__ int s_wpos[16];
    __shared__ float s_last[3];

    const int b = blockIdx.x, tid = threadIdx.x;
    const int w = tid >> 5, lane = tid & 31;
    const int base = tid * 16;

    float X[16], Y[16], Z[16], dd[16];
    int OI[16];
    {
        const float* sx = d_sx + b*NN;
        const float* sy = d_sy + b*NN;
        const float* sz = d_sz + b*NN;
        const int*   si = d_sidx + b*NN;
#pragma unroll
        for (int q = 0; q < 4; q++) {
            float4 vx = *(const float4*)(sx + base + q*4);
            float4 vy = *(const float4*)(sy + base + q*4);
            float4 vz = *(const float4*)(sz + base + q*4);
            int4   vi = *(const int4*)  (si + base + q*4);
            X[q*4+0]=vx.x; X[q*4+1]=vx.y; X[q*4+2]=vx.z; X[q*4+3]=vx.w;
            Y[q*4+0]=vy.x; Y[q*4+1]=vy.y; Y[q*4+2]=vy.z; Y[q*4+3]=vy.w;
            Z[q*4+0]=vz.x; Z[q*4+1]=vz.y; Z[q*4+2]=vz.z; Z[q*4+3]=vz.w;
            OI[q*4+0]=vi.x; OI[q*4+1]=vi.y; OI[q*4+2]=vi.z; OI[q*4+3]=vi.w;
        }
    }
#pragma unroll
    for (int i = 0; i < 16; i++) {
        s_px[base+i] = X[i]; s_py[base+i] = Y[i]; s_pz[base+i] = Z[i];
        dd[i] = 1e10f;
    }
    // warp bounding box
    float bxmin=X[0], bxmax=X[0], bymin=Y[0], bymax=Y[0], bzmin=Z[0], bzmax=Z[0];
#pragma unroll
    for (int i = 1; i < 16; i++) {
        bxmin=fminf(bxmin,X[i]); bxmax=fmaxf(bxmax,X[i]);
        bymin=fminf(bymin,Y[i]); bymax=fmaxf(bymax,Y[i]);
        bzmin=fminf(bzmin,Z[i]); bzmax=fmaxf(bzmax,Z[i]);
    }
#pragma unroll
    for (int o = 16; o >= 1; o >>= 1) {
        bxmin=fminf(bxmin,__shfl_xor_sync(0xffffffffu,bxmin,o));
        bxmax=fmaxf(bxmax,__shfl_xor_sync(0xffffffffu,bxmax,o));
        bymin=fminf(bymin,__shfl_xor_sync(0xffffffffu,bymin,o));
        bymax=fmaxf(bymax,__shfl_xor_sync(0xffffffffu,bymax,o));
        bzmin=fminf(bzmin,__shfl_xor_sync(0xffffffffu,bzmin,o));
        bzmax=fmaxf(bzmax,__shfl_xor_sync(0xffffffffu,bzmax,o));
    }
    // pack points into f32x2 pairs
    unsigned long long PX[8], PY[8], PZ[8];
#pragma unroll
    for (int j = 0; j < 8; j++) {
        PACK2(PX[j], X[2*j], X[2*j+1]);
        PACK2(PY[j], Y[2*j], Y[2*j+1]);
        PACK2(PZ[j], Z[2*j], Z[2*j+1]);
    }
    float wmaxdd = 1e10f;           // cached max(dd) in this warp

    // first center = original point 0
    float lx, ly, lz;
    {
        const float* xb = xyz + (size_t)b*NN*3;
        lx = xb[0]; ly = xb[1]; lz = xb[2];
    }
    if (tid == 0) {
        float* o = out_newxyz + (size_t)b*NPOINT*3;
        o[0] = lx; o[1] = ly; o[2] = lz;
    }
    __syncthreads();

    for (int it = 1; it < NPOINT; it++) {
        // conservative lower bound on dist2(center, any point in warp box)
        float dxl = fmaxf(fmaxf(__fadd_rn(bxmin,-lx), __fadd_rn(lx,-bxmax)), 0.0f);
        float dyl = fmaxf(fmaxf(__fadd_rn(bymin,-ly), __fadd_rn(ly,-bymax)), 0.0f);
        float dzl = fmaxf(fmaxf(__fadd_rn(bzmin,-lz), __fadd_rn(lz,-bzmax)), 0.0f);
        float dlb = (dxl*dxl + dyl*dyl + dzl*dzl) * 0.9999f;
        if (dlb < wmaxdd) {     // uniform per warp
            float nlx = -lx, nly = -ly, nlz = -lz;
            unsigned long long NLX, NLY, NLZ;
            PACK2(NLX, nlx, nlx); PACK2(NLY, nly, nly); PACK2(NLZ, nlz, nlz);
            float lv = 0.0f;
#pragma unroll
            for (int j = 0; j < 8; j++) {
                unsigned long long dx, dy, dz, qx, qy, qz, t, s;
                ADD2(dx, PX[j], NLX); ADD2(dy, PY[j], NLY); ADD2(dz, PZ[j], NLZ);
                MUL2(qx, dx, dx); MUL2(qy, dy, dy); MUL2(qz, dz, dz);
                ADD2(t, qx, qy); ADD2(s, t, qz);
                float da, db; UNPACK2(da, db, s);
                dd[2*j]   = fminf(dd[2*j],   da);
                dd[2*j+1] = fminf(dd[2*j+1], db);
                lv = fmaxf(lv, fmaxf(dd[2*j], dd[2*j+1]));
            }
            unsigned wmax = __reduce_max_sync(0xffffffffu, __float_as_uint(lv));
            unsigned cand = 0xffffffffu; int cpos = 0;
            if (__float_as_uint(lv) == wmax) {
#pragma unroll
                for (int i = 0; i < 16; i++)
                    if (__float_as_uint(dd[i]) == wmax && (unsigned)OI[i] < cand) {
                        cand = (unsigned)OI[i]; cpos = base + i;
                    }
            }
            unsigned widx = __reduce_min_sync(0xffffffffu, cand);
            if (cand == widx) s_wpos[w] = cpos;       // unique owner lane
            if (lane == 0)
                s_wkey[w] = ((unsigned long long)wmax << 32)
                          | (unsigned long long)(0xffffffffu - widx);
            wmaxdd = __uint_as_float(wmax);
        }
        __syncthreads();
        if (tid < 32) {
            unsigned long long k = (tid < 16) ? s_wkey[tid] : 0ull;
#pragma unroll
            for (int o = 16; o >= 1; o >>= 1) {
                unsigned long long ok = __shfl_xor_sync(0xffffffffu, k, o);
                if (ok > k) k = ok;
            }
            unsigned m = __ballot_sync(0xffffffffu, tid < 16 && s_wkey[tid] == k);
            if (tid == 0) {
                int gw = __ffs(m) - 1;
                int p = s_wpos[gw];
                float gx = s_px[p], gy = s_py[p], gz = s_pz[p];
                s_last[0] = gx; s_last[1] = gy; s_last[2] = gz;
                float* o2 = out_newxyz + ((size_t)b*NPOINT + it)*3;
                o2[0] = gx; o2[1] = gy; o2[2] = gz;
            }
        }
        __syncthreads();
        lx = s_last[0]; ly = s_last[1]; lz = s_last[2];
    }
}

// ---------------- ball query: warp per (b,s), first-32 in index order --------
__global__ void k_ballquery(const float* __restrict__ xyz,
                            const float* __restrict__ newxyz) {
    int warp = (blockIdx.x*blockDim.x + threadIdx.x) >> 5;
    int lane = threadIdx.x & 31;
    if (warp >= BB*NPOINT) return;
    int b = warp / NPOINT;
    const float* xb = xyz + (size_t)b*NN*3;
    const float* np = newxyz + (size_t)warp*3;
    float qx = np[0], qy = np[1], qz = np[2];
    int* outp = d_ball_idx + (size_t)warp*NSAMPLE;

    int cnt = 0, firstIdx = 0; bool haveFirst = false;
    for (int j0 = 0; j0 < NN && cnt < NSAMPLE; j0 += 32) {
        int j = j0 + lane;
        float dx = __fadd_rn(xb[j*3+0], -qx);
        float dy = __fadd_rn(xb[j*3+1], -qy);
        float dz = __fadd_rn(xb[j*3+2], -qz);
        float d = __fadd_rn(__fadd_rn(__fmul_rn(dx,dx), __fmul_rn(dy,dy)),
                            __fmul_rn(dz,dz));
        bool in = d < RADIUS2;
        unsigned m = __ballot_sync(0xffffffffu, in);
        if (m) {
            if (!haveFirst) { firstIdx = j0 + __ffs(m) - 1; haveFirst = true; }
            if (in) {
                int pos = cnt + __popc(m & ((1u << lane) - 1u));
                if (pos < NSAMPLE) outp[pos] = j;
            }
            cnt += __popc(m);
        }
    }
    int fs = cnt < NSAMPLE ? cnt : NSAMPLE;
    for (int pos = fs + lane; pos < NSAMPLE; pos += 32) outp[pos] = firstIdx;
}

// ---------------- layer 1: gather + GEMM(64x67) + stat partials --------------
__global__ __launch_bounds__(256,2) void k_layer1(const float* __restrict__ xyz,
                                                  const float* __restrict__ newxyz,
                                                  const float* __restrict__ W1) {
    extern __shared__ float sm[];
    float (*sg)[256] = (float(*)[256])sm;              // 67 x 256
    float (*sw)[64]  = (float(*)[64])(sm + 67*256);    // 67 x 64
    int tid = threadIdx.x;
    int pos0 = blockIdx.x * 256;

    for (int i = tid; i < 64*67; i += 256) { int o = i/67, c = i%67; sw[c][o] = W1[i]; }
    {
        int pos = pos0 + tid;
        int idx = d_ball_idx[pos];
        int b = pos >> 16;
        int s = (pos >> 5) & 2047;
        const float* nx = newxyz + ((size_t)b*NPOINT + s)*3;
        const float* pp = xyz + ((size_t)b*NN + idx)*3;
        sg[0][tid] = pp[0]-nx[0];
        sg[1][tid] = pp[1]-nx[1];
        sg[2][tid] = pp[2]-nx[2];
        const float4* fr = (const float4*)(d_featT + ((size_t)b*NN + idx)*CC);
#pragma unroll
        for (int c4 = 0; c4 < 16; c4++) {
            float4 v = fr[c4];
            sg[3+c4*4+0][tid] = v.x; sg[3+c4*4+1][tid] = v.y;
            sg[3+c4*4+2][tid] = v.z; sg[3+c4*4+3][tid] = v.w;
        }
    }
    __syncthreads();

    int tr = tid >> 5, tc = tid & 31;
    float acc[8][8];
#pragma unroll
    for (int i=0;i<8;i++)
#pragma unroll
        for (int j=0;j<8;j++) acc[i][j]=0.f;

#pragma unroll 2
    for (int k = 0; k < 67; k++) {
        float wv[8], g[8];
        *(float4*)&wv[0] = *(const float4*)&sw[k][tr*8];
        *(float4*)&wv[4] = *(const float4*)&sw[k][tr*8+4];
        *(float4*)&g[0] = *(const float4*)&sg[k][tc*8];
        *(float4*)&g[4] = *(const float4*)&sg[k][tc*8+4];
#pragma unroll
        for (int i=0;i<8;i++)
#pragma unroll
            for (int j=0;j<8;j++) acc[i][j] += wv[i]*g[j];
    }
#pragma unroll
    for (int i = 0; i < 8; i++) {
        int c = tr*8 + i;
        float* hp = d_h1 + (size_t)c*P_TOTAL + pos0 + tc*8;
        *(float4*)hp     = make_float4(acc[i][0],acc[i][1],acc[i][2],acc[i][3]);
        *(float4*)(hp+4) = make_float4(acc[i][4],acc[i][5],acc[i][6],acc[i][7]);
    }
#pragma unroll
    for (int i = 0; i < 8; i++) {
        float s = 0.f, q = 0.f;
#pragma unroll
        for (int j = 0; j < 8; j++) { s += acc[i][j]; q += acc[i][j]*acc[i][j]; }
#pragma unroll
        for (int o = 16; o > 0; o >>= 1) {
            s += __shfl_xor_sync(0xffffffffu, s, o);
            q += __shfl_xor_sync(0xffffffffu, q, o);
        }
        if (tc == 0) {
            int c = tr*8 + i;
            d_partials[((size_t)blockIdx.x*128 + c)*2 + 0] = s;
            d_partials[((size_t)blockIdx.x*128 + c)*2 + 1] = q;
        }
    }
}

// ---------------- deterministic stats reduce + BN fold -----------------------
__global__ void k_stats(const float* __restrict__ gam, const float* __restrict__ bet,
                        int nblocks) {
    int c = blockIdx.x, t = threadIdx.x;
    double s = 0.0, q = 0.0;
    for (int i = t; i < nblocks; i += 256) {
        s += (double)d_partials[((size_t)i*128 + c)*2 + 0];
        q += (double)d_partials[((size_t)i*128 + c)*2 + 1];
    }
    __shared__ double ss[256], qq[256];
    ss[t] = s; qq[t] = q; __syncthreads();
    for (int o = 128; o > 0; o >>= 1) {
        if (t < o) { ss[t] += ss[t+o]; qq[t] += qq[t+o]; }
        __syncthreads();
    }
    if (t == 0) {
        double mu  = ss[0] / (double)P_TOTAL;
        double var = qq[0] / (double)P_TOTAL - mu*mu;
        float a  = (float)((double)gam[c] / sqrt(var + 1e-5));
        float bp = (float)((double)bet[c] - mu * (double)a);
        d_ab[c*2] = a; d_ab[c*2+1] = bp;
    }
}

// ---------------- layer 2: bn1+relu on load, GEMM(64x64) ---------------------
__global__ __launch_bounds__(256,2) void k_layer2(const float* __restrict__ W2) {
    extern __shared__ float sm[];
    float (*sg)[256] = (float(*)[256])sm;              // 64 x 256
    float (*sw)[64]  = (float(*)[64])(sm + 64*256);    // 64 x 64
    int tid = threadIdx.x;
    int pos0 = blockIdx.x * 256;
    int wid = tid >> 5, lane = tid & 31;

    for (int i = tid; i < 64*64; i += 256) { int o = i/64, c = i%64; sw[c][o] = W2[i]; }
    for (int c = wid; c < 64; c += 8) {
        float a = d_ab[c*2], bp = d_ab[c*2+1];
        const float4* src = (const float4*)(d_h1 + (size_t)c*P_TOTAL + pos0) + lane*2;
        float4 v0 = src[0], v1 = src[1];
        v0.x=fmaxf(0.f,a*v0.x+bp); v0.y=fmaxf(0.f,a*v0.y+bp);
        v0.z=fmaxf(0.f,a*v0.z+bp); v0.w=fmaxf(0.f,a*v0.w+bp);
        v1.x=fmaxf(0.f,a*v1.x+bp); v1.y=fmaxf(0.f,a*v1.y+bp);
        v1.z=fmaxf(0.f,a*v1.z+bp); v1.w=fmaxf(0.f,a*v1.w+bp);
        *(float4*)&sg[c][lane*8]   = v0;
        *(float4*)&sg[c][lane*8+4] = v1;
    }
    __syncthreads();

    int tr = wid, tc = lane;
    float acc[8][8];
#pragma unroll
    for (int i=0;i<8;i++)
#pragma unroll
        for (int j=0;j<8;j++) acc[i][j]=0.f;
#pragma unroll 2
    for (int k = 0; k < 64; k++) {
        float wv[8], g[8];
        *(float4*)&wv[0] = *(const float4*)&sw[k][tr*8];
        *(float4*)&wv[4] = *(const float4*)&sw[k][tr*8+4];
        *(float4*)&g[0] = *(const float4*)&sg[k][tc*8];
        *(float4*)&g[4] = *(const float4*)&sg[k][tc*8+4];
#pragma unroll
        for (int i=0;i<8;i++)
#pragma unroll
            for (int j=0;j<8;j++) acc[i][j] += wv[i]*g[j];
    }
#pragma unroll
    for (int i = 0; i < 8; i++) {
        int c = tr*8 + i;
        float* hp = d_h2 + (size_t)c*P_TOTAL + pos0 + tc*8;
        *(float4*)hp     = make_float4(acc[i][0],acc[i][1],acc[i][2],acc[i][3]);
        *(float4*)(hp+4) = make_float4(acc[i][4],acc[i][5],acc[i][6],acc[i][7]);
    }
#pragma unroll
    for (int i = 0; i < 8; i++) {
        float s = 0.f, q = 0.f;
#pragma unroll
        for (int j = 0; j < 8; j++) { s += acc[i][j]; q += acc[i][j]*acc[i][j]; }
#pragma unroll
        for (int o = 16; o > 0; o >>= 1) {
            s += __shfl_xor_sync(0xffffffffu, s, o);
            q += __shfl_xor_sync(0xffffffffu, q, o);
        }
        if (tc == 0) {
            int c = tr*8 + i;
            d_partials[((size_t)blockIdx.x*128 + c)*2 + 0] = s;
            d_partials[((size_t)blockIdx.x*128 + c)*2 + 1] = q;
        }
    }
}

// ---------------- layer 3: bn2+relu on load, GEMM(128x64), fused max/min -----
__global__ __launch_bounds__(256,2) void k_layer3(const float* __restrict__ W3) {
    extern __shared__ float sm[];
    float (*sg)[128] = (float(*)[128])sm;              // 64 x 128
    float (*sw)[128] = (float(*)[128])(sm + 64*128);   // 64 x 128
    int tid = threadIdx.x;
    int pos0 = blockIdx.x * 128;
    int wid = tid >> 5, lane = tid & 31;

    for (int i = tid; i < 128*64; i += 256) { int o = i/64, c = i%64; sw[c][o] = W3[i]; }
    for (int c = wid; c < 64; c += 8) {
        float a = d_ab[c*2], bp = d_ab[c*2+1];
        const float4* src = (const float4*)(d_h2 + (size_t)c*P_TOTAL + pos0);
        float4 v = src[lane];
        v.x=fmaxf(0.f,a*v.x+bp); v.y=fmaxf(0.f,a*v.y+bp);
        v.z=fmaxf(0.f,a*v.z+bp); v.w=fmaxf(0.f,a*v.w+bp);
        *(float4*)&sg[c][lane*4] = v;
    }
    __syncthreads();

    int tr = tid >> 4, tc = tid & 15;
    float acc[8][8];
#pragma unroll
    for (int i=0;i<8;i++)
#pragma unroll
        for (int j=0;j<8;j++) acc[i][j]=0.f;
#pragma unroll 2
    for (int k = 0; k < 64; k++) {
        float wv[8], g[8];
        *(float4*)&wv[0] = *(const float4*)&sw[k][tr*8];
        *(float4*)&wv[4] = *(const float4*)&sw[k][tr*8+4];
        *(float4*)&g[0] = *(const float4*)&sg[k][tc*8];
        *(float4*)&g[4] = *(const float4*)&sg[k][tc*8+4];
#pragma unroll
        for (int i=0;i<8;i++)
#pragma unroll
            for (int j=0;j<8;j++) acc[i][j] += wv[i]*g[j];
    }
    int sglob = (pos0 >> 5) + (tc >> 2);
#pragma unroll
    for (int i = 0; i < 8; i++) {
        int c = tr*8 + i;
        float mx = acc[i][0], mn = acc[i][0];
#pragma unroll
        for (int j = 1; j < 8; j++) { mx = fmaxf(mx, acc[i][j]); mn = fminf(mn, acc[i][j]); }
        mx = fmaxf(mx, __shfl_xor_sync(0xffffffffu, mx, 1));
        mn = fminf(mn, __shfl_xor_sync(0xffffffffu, mn, 1));
        mx = fmaxf(mx, __shfl_xor_sync(0xffffffffu, mx, 2));
        mn = fminf(mn, __shfl_xor_sync(0xffffffffu, mn, 2));
        if ((tc & 3) == 0) {
            d_hmx[(size_t)c*(BB*NPOINT) + sglob] = mx;
            d_hmn[(size_t)c*(BB*NPOINT) + sglob] = mn;
        }
    }
#pragma unroll
    for (int i = 0; i < 8; i++) {
        float s = 0.f, q = 0.f;
#pragma unroll
        for (int j = 0; j < 8; j++) { s += acc[i][j]; q += acc[i][j]*acc[i][j]; }
#pragma unroll
        for (int o = 8; o > 0; o >>= 1) {
            s += __shfl_xor_sync(0xffffffffu, s, o);
            q += __shfl_xor_sync(0xffffffffu, q, o);
        }
        if (tc == 0) {
            int c = tr*8 + i;
            d_partials[((size_t)blockIdx.x*128 + c)*2 + 0] = s;
            d_partials[((size_t)blockIdx.x*128 + c)*2 + 1] = q;
        }
    }
}

// ---------------- bn3 + relu on the pooled extremum --------------------------
__global__ void k_finalize(float* __restrict__ feats) {
    int gid = blockIdx.x*blockDim.x + threadIdx.x;
    if (gid >= BB*128*NPOINT) return;
    int s = gid & 2047;
    int o = (gid >> 11) & 127;
    int b = gid >> 18;
    float a = d_ab[o*2], bp = d_ab[o*2+1];
    size_t ix = (size_t)o*(BB*NPOINT) + b*NPOINT + s;
    float v = (a >= 0.0f) ? d_hmx[ix] : d_hmn[ix];
    feats[gid] = fmaxf(0.0f, a*v + bp);
}

// ---------------- launch ------------------------------------------------------
extern "C" void kernel_launch(void* const* d_in, const int* in_sizes, int n_in,
                              void* d_out, int out_size) {
    const float* xyz      = (const float*)d_in[0];
    const float* features = (const float*)d_in[1];
    const float* W1 = (const float*)d_in[2];
    const float* g1 = (const float*)d_in[3];
    const float* b1 = (const float*)d_in[4];
    const float* W2 = (const float*)d_in[5];
    const float* g2 = (const float*)d_in[6];
    const float* b2 = (const float*)d_in[7];
    const float* W3 = (const float*)d_in[8];
    const float* g3 = (const float*)d_in[9];
    const float* b3 = (const float*)d_in[10];
    float* out    = (float*)d_out;
    float* newxyz = out;                       // 8*2048*3
    float* feats  = out + BB*NPOINT*3;         // 8*128*2048

    const int SMF = 3*NN*4;                    // 98304 for FPS point cache
    const int SM1 = (67*256 + 67*64) * 4;
    const int SM2 = (64*256 + 64*64) * 4;
    const int SM3 = (64*128 + 64*128) * 4;
    cudaFuncSetAttribute(k_fps,    cudaFuncAttributeMaxDynamicSharedMemorySize, SMF);
    cudaFuncSetAttribute(k_layer1, cudaFuncAttributeMaxDynamicSharedMemorySize, SM1);
    cudaFuncSetAttribute(k_layer2, cudaFuncAttributeMaxDynamicSharedMemorySize, SM2);
    cudaFuncSetAttribute(k_layer3, cudaFuncAttributeMaxDynamicSharedMemorySize, SM3);

    k_transpose<<<dim3(NN/32, CC/32, BB), dim3(32,8)>>>(features);
    k_sort<<<BB, 1024>>>(xyz);
    k_fps<<<BB, 512, SMF>>>(xyz, newxyz);
    k_ballquery<<<(BB*NPOINT)/4, 128>>>(xyz, newxyz);

    k_layer1<<<P_TOTAL/256, 256, SM1>>>(xyz, newxyz, W1);
    k_stats<<<64, 256>>>(g1, b1, P_TOTAL/256);
    k_layer2<<<P_TOTAL/256, 256, SM2>>>(W2);
    k_stats<<<64, 256>>>(g2, b2, P_TOTAL/256);
    k_layer3<<<P_TOTAL/128, 256, SM3>>>(W3);
    k_stats<<<128, 256>>>(g3, b3, P_TOTAL/128);
    k_finalize<<<(BB*128*NPOINT)/256, 256>>>(feats);
}

// round 4
// speedup vs baseline: 2.5802x; 1.0902x over previous
#include <cuda_runtime.h>
#include <stdint.h>

#define BB 8
#define NN 8192
#define CC 64
#define NPOINT 2048
#define NSAMPLE 32
#define RADIUS2 0.04f
#define P_TOTAL (BB*NPOINT*NSAMPLE)   // 524288

// ---------------- scratch (device globals; no allocation allowed) ------------
__device__ float d_featT[BB*NN*CC];                 // 16.8 MB  (B,N,C)
__device__ int   d_ball_idx[P_TOTAL];
__device__ float d_h1[(size_t)64*P_TOTAL];          // 134 MB
__device__ float d_h2[(size_t)64*P_TOTAL];          // 134 MB
__device__ float d_hmx[(size_t)128*BB*NPOINT];      // 8 MB
__device__ float d_hmn[(size_t)128*BB*NPOINT];      // 8 MB
__device__ float d_partials[4096*128*2];            // 4 MB
__device__ float d_ab[128*2];                       // fused BN scale/shift
// Morton-sorted copies of xyz (+ original index)
__device__ float d_sx[BB*NN], d_sy[BB*NN], d_sz[BB*NN];
__device__ int   d_sidx[BB*NN];

// ---------------- packed f32x2 helpers (exact per-element RN) ----------------
#define PACK2(out, lo, hi)  asm("mov.b64 %0, {%1, %2};" : "=l"(out) : "f"(lo), "f"(hi))
#define UNPACK2(lo, hi, in) asm("mov.b64 {%0, %1}, %2;" : "=f"(lo), "=f"(hi) : "l"(in))
#define ADD2(out, a, b)     asm("add.rn.f32x2 %0, %1, %2;" : "=l"(out) : "l"(a), "l"(b))
#define MUL2(out, a, b)     asm("mul.rn.f32x2 %0, %1, %2;" : "=l"(out) : "l"(a), "l"(b))

// ---------------- feature transpose (B,C,N) -> (B,N,C) -----------------------
__global__ void k_transpose(const float* __restrict__ f) {
    __shared__ float tile[32][33];
    int b = blockIdx.z, n0 = blockIdx.x*32, c0 = blockIdx.y*32;
    int tx = threadIdx.x, ty = threadIdx.y;
    for (int i = ty; i < 32; i += 8)
        tile[i][tx] = f[((size_t)b*CC + c0 + i)*NN + n0 + tx];
    __syncthreads();
    for (int i = ty; i < 32; i += 8)
        d_featT[((size_t)b*NN + n0 + i)*CC + c0 + tx] = tile[tx][i];
}

// ---------------- Morton counting sort: one CTA per batch --------------------
__global__ __launch_bounds__(1024,1) void k_sort(const float* __restrict__ xyz) {
    __shared__ int cnt[4096];
    __shared__ unsigned short cell[8192];
    __shared__ int wsum[32];
    int b = blockIdx.x, t = threadIdx.x;
    for (int i = t; i < 4096; i += 1024) cnt[i] = 0;
    __syncthreads();
    const float* xb = xyz + (size_t)b*NN*3;
    for (int i = t; i < NN; i += 1024) {
        float x = xb[i*3+0], y = xb[i*3+1], z = xb[i*3+2];
        int cx = min(15, max(0, (int)(x*16.0f)));
        int cy = min(15, max(0, (int)(y*16.0f)));
        int cz = min(15, max(0, (int)(z*16.0f)));
        int m = 0;
#pragma unroll
        for (int j = 0; j < 4; j++)
            m |= (((cx>>j)&1)<<(3*j)) | (((cy>>j)&1)<<(3*j+1)) | (((cz>>j)&1)<<(3*j+2));
        cell[i] = (unsigned short)m;
        atomicAdd(&cnt[m], 1);
    }
    __syncthreads();
    int c0 = cnt[t*4+0], c1 = cnt[t*4+1], c2 = cnt[t*4+2], c3 = cnt[t*4+3];
    int ts = c0+c1+c2+c3;
    int lane = t & 31, w = t >> 5;
    int x = ts;
#pragma unroll
    for (int o = 1; o < 32; o <<= 1) {
        int y = __shfl_up_sync(0xffffffffu, x, o);
        if (lane >= o) x += y;
    }
    if (lane == 31) wsum[w] = x;
    int wex = x - ts;
    __syncthreads();
    if (w == 0) {
        int v = wsum[lane];
        int xx = v;
#pragma unroll
        for (int o = 1; o < 32; o <<= 1) {
            int y = __shfl_up_sync(0xffffffffu, xx, o);
            if (lane >= o) xx += y;
        }
        wsum[lane] = xx - v;
    }
    __syncthreads();
    int basep = wsum[w] + wex;
    cnt[t*4+0] = basep;
    cnt[t*4+1] = basep + c0;
    cnt[t*4+2] = basep + c0 + c1;
    cnt[t*4+3] = basep + c0 + c1 + c2;
    __syncthreads();
    for (int i = t; i < NN; i += 1024) {
        int m = cell[i];
        int pos = atomicAdd(&cnt[m], 1);
        d_sx[b*NN+pos] = xb[i*3+0];
        d_sy[b*NN+pos] = xb[i*3+1];
        d_sz[b*NN+pos] = xb[i*3+2];
        d_sidx[b*NN+pos] = i;
    }
}

// ---------------- FPS: 1 CTA/batch, 512 thr ----------------------------------
// Warp owns 512 Morton-contiguous points, split in two 256-pt halves with
// independent bounding boxes + cached (wmax,key). One __syncthreads per
// iteration; winner reduced redundantly by every warp via u32 REDUX over
// parity-double-buffered (val,key) smem slots.
__global__ __launch_bounds__(512,1) void k_fps(const float* __restrict__ xyz,
                                               float* __restrict__ out_newxyz) {
    extern __shared__ float smem[];
    float* s_px = smem;              // 8192
    float* s_py = smem + 8192;
    float* s_pz = smem + 16384;
    int*   s_oi = (int*)(smem + 24576);
    __shared__ unsigned s_val[2][16];
    __shared__ unsigned s_key[2][16];

    const int b = blockIdx.x, tid = threadIdx.x;
    const int w = tid >> 5, lane = tid & 31;
    const int baseA = w*512 + lane*8;
    const int baseB = baseA + 256;

    float XA[8], YA[8], ZA[8], XB[8], YB[8], ZB[8];
    float ddA[8], ddB[8];
    {
        const float* sx = d_sx + b*NN;
        const float* sy = d_sy + b*NN;
        const float* sz = d_sz + b*NN;
        const int*   si = d_sidx + b*NN;
#pragma unroll
        for (int q = 0; q < 2; q++) {
            float4 vx = *(const float4*)(sx + baseA + q*4);
            float4 vy = *(const float4*)(sy + baseA + q*4);
            float4 vz = *(const float4*)(sz + baseA + q*4);
            XA[q*4+0]=vx.x; XA[q*4+1]=vx.y; XA[q*4+2]=vx.z; XA[q*4+3]=vx.w;
            YA[q*4+0]=vy.x; YA[q*4+1]=vy.y; YA[q*4+2]=vy.z; YA[q*4+3]=vy.w;
            ZA[q*4+0]=vz.x; ZA[q*4+1]=vz.y; ZA[q*4+2]=vz.z; ZA[q*4+3]=vz.w;
            float4 wx = *(const float4*)(sx + baseB + q*4);
            float4 wy = *(const float4*)(sy + baseB + q*4);
            float4 wz = *(const float4*)(sz + baseB + q*4);
            XB[q*4+0]=wx.x; XB[q*4+1]=wx.y; XB[q*4+2]=wx.z; XB[q*4+3]=wx.w;
            YB[q*4+0]=wy.x; YB[q*4+1]=wy.y; YB[q*4+2]=wy.z; YB[q*4+3]=wy.w;
            ZB[q*4+0]=wz.x; ZB[q*4+1]=wz.y; ZB[q*4+2]=wz.z; ZB[q*4+3]=wz.w;
        }
#pragma unroll
        for (int i = 0; i < 8; i++) {
            s_px[baseA+i]=XA[i]; s_py[baseA+i]=YA[i]; s_pz[baseA+i]=ZA[i];
            s_px[baseB+i]=XB[i]; s_py[baseB+i]=YB[i]; s_pz[baseB+i]=ZB[i];
            s_oi[baseA+i]=si[baseA+i]; s_oi[baseB+i]=si[baseB+i];
            ddA[i]=1e10f; ddB[i]=1e10f;
        }
    }
    // per-half bounding boxes (warp reduce)
    float axn=XA[0],axx=XA[0],ayn=YA[0],ayx=YA[0],azn=ZA[0],azx=ZA[0];
    float bxn=XB[0],bxx=XB[0],byn=YB[0],byx=YB[0],bzn=ZB[0],bzx=ZB[0];
#pragma unroll
    for (int i = 1; i < 8; i++) {
        axn=fminf(axn,XA[i]); axx=fmaxf(axx,XA[i]);
        ayn=fminf(ayn,YA[i]); ayx=fmaxf(ayx,YA[i]);
        azn=fminf(azn,ZA[i]); azx=fmaxf(azx,ZA[i]);
        bxn=fminf(bxn,XB[i]); bxx=fmaxf(bxx,XB[i]);
        byn=fminf(byn,YB[i]); byx=fmaxf(byx,YB[i]);
        bzn=fminf(bzn,ZB[i]); bzx=fmaxf(bzx,ZB[i]);
    }
#pragma unroll
    for (int o = 16; o >= 1; o >>= 1) {
        axn=fminf(axn,__shfl_xor_sync(0xffffffffu,axn,o));
        axx=fmaxf(axx,__shfl_xor_sync(0xffffffffu,axx,o));
        ayn=fminf(ayn,__shfl_xor_sync(0xffffffffu,ayn,o));
        ayx=fmaxf(ayx,__shfl_xor_sync(0xffffffffu,ayx,o));
        azn=fminf(azn,__shfl_xor_sync(0xffffffffu,azn,o));
        azx=fmaxf(azx,__shfl_xor_sync(0xffffffffu,azx,o));
        bxn=fminf(bxn,__shfl_xor_sync(0xffffffffu,bxn,o));
        bxx=fmaxf(bxx,__shfl_xor_sync(0xffffffffu,bxx,o));
        byn=fminf(byn,__shfl_xor_sync(0xffffffffu,byn,o));
        byx=fmaxf(byx,__shfl_xor_sync(0xffffffffu,byx,o));
        bzn=fminf(bzn,__shfl_xor_sync(0xffffffffu,bzn,o));
        bzx=fmaxf(bzx,__shfl_xor_sync(0xffffffffu,bzx,o));
    }
    // pack into f32x2
    unsigned long long PXA[4],PYA[4],PZA[4],PXB[4],PYB[4],PZB[4];
#pragma unroll
    for (int j = 0; j < 4; j++) {
        PACK2(PXA[j],XA[2*j],XA[2*j+1]); PACK2(PYA[j],YA[2*j],YA[2*j+1]); PACK2(PZA[j],ZA[2*j],ZA[2*j+1]);
        PACK2(PXB[j],XB[2*j],XB[2*j+1]); PACK2(PYB[j],YB[2*j],YB[2*j+1]); PACK2(PZB[j],ZB[2*j],ZB[2*j+1]);
    }
    unsigned wmaxA = __float_as_uint(1e10f), keyA = 0xffffffffu;
    unsigned wmaxB = __float_as_uint(1e10f), keyB = 0xffffffffu;

    float lx, ly, lz;
    {
        const float* xb = xyz + (size_t)b*NN*3;
        lx = xb[0]; ly = xb[1]; lz = xb[2];
    }
    if (tid == 0) {
        float* o = out_newxyz + (size_t)b*NPOINT*3;
        o[0] = lx; o[1] = ly; o[2] = lz;
    }

    for (int it = 1; it < NPOINT; it++) {
        const int par = it & 1;
        float nlx = -lx, nly = -ly, nlz = -lz;
        unsigned long long NLX, NLY, NLZ;
        PACK2(NLX,nlx,nlx); PACK2(NLY,nly,nly); PACK2(NLZ,nlz,nlz);

        // ---- half A ----
        {
            float dxl = fmaxf(fmaxf(__fadd_rn(axn,-lx), __fadd_rn(lx,-axx)), 0.0f);
            float dyl = fmaxf(fmaxf(__fadd_rn(ayn,-ly), __fadd_rn(ly,-ayx)), 0.0f);
            float dzl = fmaxf(fmaxf(__fadd_rn(azn,-lz), __fadd_rn(lz,-azx)), 0.0f);
            float dlb = (dxl*dxl + dyl*dyl + dzl*dzl) * 0.9999f;
            if (dlb < __uint_as_float(wmaxA)) {
                float lv = 0.0f;
#pragma unroll
                for (int j = 0; j < 4; j++) {
                    unsigned long long dx,dy,dz,qx,qy,qz,t,s;
                    ADD2(dx,PXA[j],NLX); ADD2(dy,PYA[j],NLY); ADD2(dz,PZA[j],NLZ);
                    MUL2(qx,dx,dx); MUL2(qy,dy,dy); MUL2(qz,dz,dz);
                    ADD2(t,qx,qy); ADD2(s,t,qz);
                    float da,db; UNPACK2(da,db,s);
                    ddA[2*j]   = fminf(ddA[2*j],da);
                    ddA[2*j+1] = fminf(ddA[2*j+1],db);
                    lv = fmaxf(lv, fmaxf(ddA[2*j], ddA[2*j+1]));
                }
                wmaxA = __reduce_max_sync(0xffffffffu, __float_as_uint(lv));
                unsigned cand = 0xffffffffu;
                if (__float_as_uint(lv) == wmaxA) {
#pragma unroll
                    for (int i = 0; i < 8; i++)
                        if (__float_as_uint(ddA[i]) == wmaxA) {
                            unsigned k = ((unsigned)s_oi[baseA+i] << 13) | (unsigned)(baseA+i);
                            cand = min(cand, k);
                        }
                }
                keyA = __reduce_min_sync(0xffffffffu, cand);
            }
        }
        // ---- half B ----
        {
            float dxl = fmaxf(fmaxf(__fadd_rn(bxn,-lx), __fadd_rn(lx,-bxx)), 0.0f);
            float dyl = fmaxf(fmaxf(__fadd_rn(byn,-ly), __fadd_rn(ly,-byx)), 0.0f);
            float dzl = fmaxf(fmaxf(__fadd_rn(bzn,-lz), __fadd_rn(lz,-bzx)), 0.0f);
            float dlb = (dxl*dxl + dyl*dyl + dzl*dzl) * 0.9999f;
            if (dlb < __uint_as_float(wmaxB)) {
                float lv = 0.0f;
#pragma unroll
                for (int j = 0; j < 4; j++) {
                    unsigned long long dx,dy,dz,qx,qy,qz,t,s;
                    ADD2(dx,PXB[j],NLX); ADD2(dy,PYB[j],NLY); ADD2(dz,PZB[j],NLZ);
                    MUL2(qx,dx,dx); MUL2(qy,dy,dy); MUL2(qz,dz,dz);
                    ADD2(t,qx,qy); ADD2(s,t,qz);
                    float da,db; UNPACK2(da,db,s);
                    ddB[2*j]   = fminf(ddB[2*j],da);
                    ddB[2*j+1] = fminf(ddB[2*j+1],db);
                    lv = fmaxf(lv, fmaxf(ddB[2*j], ddB[2*j+1]));
                }
                wmaxB = __reduce_max_sync(0xffffffffu, __float_as_uint(lv));
                unsigned cand = 0xffffffffu;
                if (__float_as_uint(lv) == wmaxB) {
#pragma unroll
                    for (int i = 0; i < 8; i++)
                        if (__float_as_uint(ddB[i]) == wmaxB) {
                            unsigned k = ((unsigned)s_oi[baseB+i] << 13) | (unsigned)(baseB+i);
                            cand = min(cand, k);
                        }
                }
                keyB = __reduce_min_sync(0xffffffffu, cand);
            }
        }
        // combine halves (max val; tie -> min key)
        unsigned bv, bk;
        if (wmaxA > wmaxB || (wmaxA == wmaxB && keyA < keyB)) { bv = wmaxA; bk = keyA; }
        else                                                   { bv = wmaxB; bk = keyB; }
        if (lane == 0) { s_val[par][w] = bv; s_key[par][w] = bk; }
        __syncthreads();
        // redundant global reduce in every warp
        unsigned v  = (lane < 16) ? s_val[par][lane] : 0u;
        unsigned m  = __reduce_max_sync(0xffffffffu, v);
        unsigned ck = (lane < 16 && v == m) ? s_key[par][lane] : 0xffffffffu;
        unsigned gk = __reduce_min_sync(0xffffffffu, ck);
        int p = (int)(gk & 8191u);
        lx = s_px[p]; ly = s_py[p]; lz = s_pz[p];
        if (tid == 0) {
            float* o2 = out_newxyz + ((size_t)b*NPOINT + it)*3;
            o2[0] = lx; o2[1] = ly; o2[2] = lz;
        }
    }
}

// ---------------- ball query: smem-staged, 16 queries per 512-thr CTA --------
__global__ __launch_bounds__(512,2) void k_ballquery(const float* __restrict__ xyz,
                                                     const float* __restrict__ newxyz) {
    extern __shared__ float sm[];
    float* sx = sm;            // 8192
    float* sy = sm + 8192;
    float* sz = sm + 16384;
    int tid = threadIdx.x;
    int b = blockIdx.x >> 7;            // /128
    int qbase = (blockIdx.x & 127) * 16;

    // stage batch xyz (AoS -> SoA)
    const float4* src = (const float4*)(xyz + (size_t)b*NN*3);
    for (int i = tid; i < NN*3/4; i += 512) {
        float4 v = src[i];
        int e = 4*i;
#pragma unroll
        for (int k = 0; k < 4; k++) {
            float val = (k==0)?v.x:(k==1)?v.y:(k==2)?v.z:v.w;
            int e2 = e + k;
            int p = e2/3, c = e2 - p*3;
            if (c == 0) sx[p] = val; else if (c == 1) sy[p] = val; else sz[p] = val;
        }
    }
    __syncthreads();

    int w = tid >> 5, lane = tid & 31;
    int s = qbase + w;
    int gq = b*NPOINT + s;
    const float* np = newxyz + (size_t)gq*3;
    float qx = np[0], qy = np[1], qz = np[2];
    int* outp = d_ball_idx + (size_t)gq*NSAMPLE;

    int cnt = 0, firstIdx = 0; bool haveFirst = false;
    for (int j0 = 0; j0 < NN && cnt < NSAMPLE; j0 += 32) {
        int j = j0 + lane;
        float dx = __fadd_rn(sx[j], -qx);
        float dy = __fadd_rn(sy[j], -qy);
        float dz = __fadd_rn(sz[j], -qz);
        float d = __fadd_rn(__fadd_rn(__fmul_rn(dx,dx), __fmul_rn(dy,dy)),
                            __fmul_rn(dz,dz));
        bool in = d < RADIUS2;
        unsigned mm = __ballot_sync(0xffffffffu, in);
        if (mm) {
            if (!haveFirst) { firstIdx = j0 + __ffs(mm) - 1; haveFirst = true; }
            if (in) {
                int pos = cnt + __popc(mm & ((1u << lane) - 1u));
                if (pos < NSAMPLE) outp[pos] = j;
            }
            cnt += __popc(mm);
        }
    }
    int fs = cnt < NSAMPLE ? cnt : NSAMPLE;
    for (int pos = fs + lane; pos < NSAMPLE; pos += 32) outp[pos] = firstIdx;
}

// ---------------- layer 1: gather + GEMM(64x67) + stat partials --------------
__global__ __launch_bounds__(256,2) void k_layer1(const float* __restrict__ xyz,
                                                  const float* __restrict__ newxyz,
                                                  const float* __restrict__ W1) {
    extern __shared__ float sm[];
    float (*sg)[256] = (float(*)[256])sm;              // 67 x 256
    float (*sw)[64]  = (float(*)[64])(sm + 67*256);    // 67 x 64
    int tid = threadIdx.x;
    int pos0 = blockIdx.x * 256;

    for (int i = tid; i < 64*67; i += 256) { int o = i/67, c = i%67; sw[c][o] = W1[i]; }
    {
        int pos = pos0 + tid;
        int idx = d_ball_idx[pos];
        int b = pos >> 16;
        int s = (pos >> 5) & 2047;
        const float* nx = newxyz + ((size_t)b*NPOINT + s)*3;
        const float* pp = xyz + ((size_t)b*NN + idx)*3;
        sg[0][tid] = pp[0]-nx[0];
        sg[1][tid] = pp[1]-nx[1];
        sg[2][tid] = pp[2]-nx[2];
        const float4* fr = (const float4*)(d_featT + ((size_t)b*NN + idx)*CC);
#pragma unroll
        for (int c4 = 0; c4 < 16; c4++) {
            float4 v = fr[c4];
            sg[3+c4*4+0][tid] = v.x; sg[3+c4*4+1][tid] = v.y;
            sg[3+c4*4+2][tid] = v.z; sg[3+c4*4+3][tid] = v.w;
        }
    }
    __syncthreads();

    int tr = tid >> 5, tc = tid & 31;
    float acc[8][8];
#pragma unroll
    for (int i=0;i<8;i++)
#pragma unroll
        for (int j=0;j<8;j++) acc[i][j]=0.f;

#pragma unroll 2
    for (int k = 0; k < 67; k++) {
        float wv[8], g[8];
        *(float4*)&wv[0] = *(const float4*)&sw[k][tr*8];
        *(float4*)&wv[4] = *(const float4*)&sw[k][tr*8+4];
        *(float4*)&g[0] = *(const float4*)&sg[k][tc*8];
        *(float4*)&g[4] = *(const float4*)&sg[k][tc*8+4];
#pragma unroll
        for (int i=0;i<8;i++)
#pragma unroll
            for (int j=0;j<8;j++) acc[i][j] += wv[i]*g[j];
    }
#pragma unroll
    for (int i = 0; i < 8; i++) {
        int c = tr*8 + i;
        float* hp = d_h1 + (size_t)c*P_TOTAL + pos0 + tc*8;
        *(float4*)hp     = make_float4(acc[i][0],acc[i][1],acc[i][2],acc[i][3]);
        *(float4*)(hp+4) = make_float4(acc[i][4],acc[i][5],acc[i][6],acc[i][7]);
    }
#pragma unroll
    for (int i = 0; i < 8; i++) {
        float s = 0.f, q = 0.f;
#pragma unroll
        for (int j = 0; j < 8; j++) { s += acc[i][j]; q += acc[i][j]*acc[i][j]; }
#pragma unroll
        for (int o = 16; o > 0; o >>= 1) {
            s += __shfl_xor_sync(0xffffffffu, s, o);
            q += __shfl_xor_sync(0xffffffffu, q, o);
        }
        if (tc == 0) {
            int c = tr*8 + i;
            d_partials[((size_t)blockIdx.x*128 + c)*2 + 0] = s;
            d_partials[((size_t)blockIdx.x*128 + c)*2 + 1] = q;
        }
    }
}

// ---------------- deterministic stats reduce + BN fold -----------------------
__global__ void k_stats(const float* __restrict__ gam, const float* __restrict__ bet,
                        int nblocks) {
    int c = blockIdx.x, t = threadIdx.x;
    double s = 0.0, q = 0.0;
    for (int i = t; i < nblocks; i += 256) {
        s += (double)d_partials[((size_t)i*128 + c)*2 + 0];
        q += (double)d_partials[((size_t)i*128 + c)*2 + 1];
    }
    __shared__ double ss[256], qq[256];
    ss[t] = s; qq[t] = q; __syncthreads();
    for (int o = 128; o > 0; o >>= 1) {
        if (t < o) { ss[t] += ss[t+o]; qq[t] += qq[t+o]; }
        __syncthreads();
    }
    if (t == 0) {
        double mu  = ss[0] / (double)P_TOTAL;
        double var = qq[0] / (double)P_TOTAL - mu*mu;
        float a  = (float)((double)gam[c] / sqrt(var + 1e-5));
        float bp = (float)((double)bet[c] - mu * (double)a);
        d_ab[c*2] = a; d_ab[c*2+1] = bp;
    }
}

// ---------------- layer 2: bn1+relu on load, GEMM(64x64) ---------------------
__global__ __launch_bounds__(256,2) void k_layer2(const float* __restrict__ W2) {
    extern __shared__ float sm[];
    float (*sg)[256] = (float(*)[256])sm;              // 64 x 256
    float (*sw)[64]  = (float(*)[64])(sm + 64*256);    // 64 x 64
    int tid = threadIdx.x;
    int pos0 = blockIdx.x * 256;
    int wid = tid >> 5, lane = tid & 31;

    for (int i = tid; i < 64*64; i += 256) { int o = i/64, c = i%64; sw[c][o] = W2[i]; }
    for (int c = wid; c < 64; c += 8) {
        float a = d_ab[c*2], bp = d_ab[c*2+1];
        const float4* src = (const float4*)(d_h1 + (size_t)c*P_TOTAL + pos0) + lane*2;
        float4 v0 = src[0], v1 = src[1];
        v0.x=fmaxf(0.f,a*v0.x+bp); v0.y=fmaxf(0.f,a*v0.y+bp);
        v0.z=fmaxf(0.f,a*v0.z+bp); v0.w=fmaxf(0.f,a*v0.w+bp);
        v1.x=fmaxf(0.f,a*v1.x+bp); v1.y=fmaxf(0.f,a*v1.y+bp);
        v1.z=fmaxf(0.f,a*v1.z+bp); v1.w=fmaxf(0.f,a*v1.w+bp);
        *(float4*)&sg[c][lane*8]   = v0;
        *(float4*)&sg[c][lane*8+4] = v1;
    }
    __syncthreads();

    int tr = wid, tc = lane;
    float acc[8][8];
#pragma unroll
    for (int i=0;i<8;i++)
#pragma unroll
        for (int j=0;j<8;j++) acc[i][j]=0.f;
#pragma unroll 2
    for (int k = 0; k < 64; k++) {
        float wv[8], g[8];
        *(float4*)&wv[0] = *(const float4*)&sw[k][tr*8];
        *(float4*)&wv[4] = *(const float4*)&sw[k][tr*8+4];
        *(float4*)&g[0] = *(const float4*)&sg[k][tc*8];
        *(float4*)&g[4] = *(const float4*)&sg[k][tc*8+4];
#pragma unroll
        for (int i=0;i<8;i++)
#pragma unroll
            for (int j=0;j<8;j++) acc[i][j] += wv[i]*g[j];
    }
#pragma unroll
    for (int i = 0; i < 8; i++) {
        int c = tr*8 + i;
        float* hp = d_h2 + (size_t)c*P_TOTAL + pos0 + tc*8;
        *(float4*)hp     = make_float4(acc[i][0],acc[i][1],acc[i][2],acc[i][3]);
        *(float4*)(hp+4) = make_float4(acc[i][4],acc[i][5],acc[i][6],acc[i][7]);
    }
#pragma unroll
    for (int i = 0; i < 8; i++) {
        float s = 0.f, q = 0.f;
#pragma unroll
        for (int j = 0; j < 8; j++) { s += acc[i][j]; q += acc[i][j]*acc[i][j]; }
#pragma unroll
        for (int o = 16; o > 0; o >>= 1) {
            s += __shfl_xor_sync(0xffffffffu, s, o);
            q += __shfl_xor_sync(0xffffffffu, q, o);
        }
        if (tc == 0) {
            int c = tr*8 + i;
            d_partials[((size_t)blockIdx.x*128 + c)*2 + 0] = s;
            d_partials[((size_t)blockIdx.x*128 + c)*2 + 1] = q;
        }
    }
}

// ---------------- layer 3: bn2+relu on load, GEMM(128x64), fused max/min -----
__global__ __launch_bounds__(256,2) void k_layer3(const float* __restrict__ W3) {
    extern __shared__ float sm[];
    float (*sg)[128] = (float(*)[128])sm;              // 64 x 128
    float (*sw)[128] = (float(*)[128])(sm + 64*128);   // 64 x 128
    int tid = threadIdx.x;
    int pos0 = blockIdx.x * 128;
    int wid = tid >> 5, lane = tid & 31;

    for (int i = tid; i < 128*64; i += 256) { int o = i/64, c = i%64; sw[c][o] = W3[i]; }
    for (int c = wid; c < 64; c += 8) {
        float a = d_ab[c*2], bp = d_ab[c*2+1];
        const float4* src = (const float4*)(d_h2 + (size_t)c*P_TOTAL + pos0);
        float4 v = src[lane];
        v.x=fmaxf(0.f,a*v.x+bp); v.y=fmaxf(0.f,a*v.y+bp);
        v.z=fmaxf(0.f,a*v.z+bp); v.w=fmaxf(0.f,a*v.w+bp);
        *(float4*)&sg[c][lane*4] = v;
    }
    __syncthreads();

    int tr = tid >> 4, tc = tid & 15;
    float acc[8][8];
#pragma unroll
    for (int i=0;i<8;i++)
#pragma unroll
        for (int j=0;j<8;j++) acc[i][j]=0.f;
#pragma unroll 2
    for (int k = 0; k < 64; k++) {
        float wv[8], g[8];
        *(float4*)&wv[0] = *(const float4*)&sw[k][tr*8];
        *(float4*)&wv[4] = *(const float4*)&sw[k][tr*8+4];
        *(float4*)&g[0] = *(const float4*)&sg[k][tc*8];
        *(float4*)&g[4] = *(const float4*)&sg[k][tc*8+4];
#pragma unroll
        for (int i=0;i<8;i++)
#pragma unroll
            for (int j=0;j<8;j++) acc[i][j] += wv[i]*g[j];
    }
    int sglob = (pos0 >> 5) + (tc >> 2);
#pragma unroll
    for (int i = 0; i < 8; i++) {
        int c = tr*8 + i;
        float mx = acc[i][0], mn = acc[i][0];
#pragma unroll
        for (int j = 1; j < 8; j++) { mx = fmaxf(mx, acc[i][j]); mn = fminf(mn, acc[i][j]); }
        mx = fmaxf(mx, __shfl_xor_sync(0xffffffffu, mx, 1));
        mn = fminf(mn, __shfl_xor_sync(0xffffffffu, mn, 1));
        mx = fmaxf(mx, __shfl_xor_sync(0xffffffffu, mx, 2));
        mn = fminf(mn, __shfl_xor_sync(0xffffffffu, mn, 2));
        if ((tc & 3) == 0) {
            d_hmx[(size_t)c*(BB*NPOINT) + sglob] = mx;
            d_hmn[(size_t)c*(BB*NPOINT) + sglob] = mn;
        }
    }
#pragma unroll
    for (int i = 0; i < 8; i++) {
        float s = 0.f, q = 0.f;
#pragma unroll
        for (int j = 0; j < 8; j++) { s += acc[i][j]; q += acc[i][j]*acc[i][j]; }
#pragma unroll
        for (int o = 8; o > 0; o >>= 1) {
            s += __shfl_xor_sync(0xffffffffu, s, o);
            q += __shfl_xor_sync(0xffffffffu, q, o);
        }
        if (tc == 0) {
            int c = tr*8 + i;
            d_partials[((size_t)blockIdx.x*128 + c)*2 + 0] = s;
            d_partials[((size_t)blockIdx.x*128 + c)*2 + 1] = q;
        }
    }
}

// ---------------- bn3 + relu on the pooled extremum --------------------------
__global__ void k_finalize(float* __restrict__ feats) {
    int gid = blockIdx.x*blockDim.x + threadIdx.x;
    if (gid >= BB*128*NPOINT) return;
    int s = gid & 2047;
    int o = (gid >> 11) & 127;
    int b = gid >> 18;
    float a = d_ab[o*2], bp = d_ab[o*2+1];
    size_t ix = (size_t)o*(BB*NPOINT) + b*NPOINT + s;
    float v = (a >= 0.0f) ? d_hmx[ix] : d_hmn[ix];
    feats[gid] = fmaxf(0.0f, a*v + bp);
}

// ---------------- launch ------------------------------------------------------
extern "C" void kernel_launch(void* const* d_in, const int* in_sizes, int n_in,
                              void* d_out, int out_size) {
    const float* xyz      = (const float*)d_in[0];
    const float* features = (const float*)d_in[1];
    const float* W1 = (const float*)d_in[2];
    const float* g1 = (const float*)d_in[3];
    const float* b1 = (const float*)d_in[4];
    const float* W2 = (const float*)d_in[5];
    const float* g2 = (const float*)d_in[6];
    const float* b2 = (const float*)d_in[7];
    const float* W3 = (const float*)d_in[8];
    const float* g3 = (const float*)d_in[9];
    const float* b3 = (const float*)d_in[10];
    float* out    = (float*)d_out;
    float* newxyz = out;                       // 8*2048*3
    float* feats  = out + BB*NPOINT*3;         // 8*128*2048

    const int SMF = 4*NN*4;                    // 128KB: px,py,pz,oi
    const int SMQ = 3*NN*4;                    // 96KB for ballquery stage
    const int SM1 = (67*256 + 67*64) * 4;
    const int SM2 = (64*256 + 64*64) * 4;
    const int SM3 = (64*128 + 64*128) * 4;
    cudaFuncSetAttribute(k_fps,       cudaFuncAttributeMaxDynamicSharedMemorySize, SMF);
    cudaFuncSetAttribute(k_ballquery, cudaFuncAttributeMaxDynamicSharedMemorySize, SMQ);
    cudaFuncSetAttribute(k_layer1,    cudaFuncAttributeMaxDynamicSharedMemorySize, SM1);
    cudaFuncSetAttribute(k_layer2,    cudaFuncAttributeMaxDynamicSharedMemorySize, SM2);
    cudaFuncSetAttribute(k_layer3,    cudaFuncAttributeMaxDynamicSharedMemorySize, SM3);

    k_transpose<<<dim3(NN/32, CC/32, BB), dim3(32,8)>>>(features);
    k_sort<<<BB, 1024>>>(xyz);
    k_fps<<<BB, 512, SMF>>>(xyz, newxyz);
    k_ballquery<<<BB*128, 512, SMQ>>>(xyz, newxyz);

    k_layer1<<<P_TOTAL/256, 256, SM1>>>(xyz, newxyz, W1);
    k_stats<<<64, 256>>>(g1, b1, P_TOTAL/256);
    k_layer2<<<P_TOTAL/256, 256, SM2>>>(W2);
    k_stats<<<64, 256>>>(g2, b2, P_TOTAL/256);
    k_layer3<<<P_TOTAL/128, 256, SM3>>>(W3);
    k_stats<<<128, 256>>>(g3, b3, P_TOTAL/128);
    k_finalize<<<(BB*128*NPOINT)/256, 256>>>(feats);
}

// round 5
// speedup vs baseline: 2.8019x; 1.0859x over previous
#include <cuda_runtime.h>
#include <stdint.h>

#define BB 8
#define NN 8192
#define CC 64
#define NPOINT 2048
#define NSAMPLE 32
#define RADIUS2 0.04f
#define P_TOTAL (BB*NPOINT*NSAMPLE)   // 524288

// ---------------- scratch (device globals; no allocation allowed) ------------
__device__ float d_featT[BB*NN*CC];                 // 16.8 MB  (B,N,C)
__device__ int   d_ball_idx[P_TOTAL];
__device__ float d_h1[(size_t)64*P_TOTAL];          // 134 MB
__device__ float d_h2[(size_t)64*P_TOTAL];          // 134 MB
__device__ float d_hmx[(size_t)128*BB*NPOINT];      // 8 MB
__device__ float d_hmn[(size_t)128*BB*NPOINT];      // 8 MB
__device__ float d_partials[4096*128*2];            // 4 MB
__device__ float d_ab[128*2];                       // fused BN scale/shift
// Morton-sorted copies of xyz (+ original index)
__device__ float d_sx[BB*NN], d_sy[BB*NN], d_sz[BB*NN];
__device__ int   d_sidx[BB*NN];

// ---------------- packed f32x2 helpers (exact per-element RN) ----------------
#define PACK2(out, lo, hi)  asm("mov.b64 %0, {%1, %2};" : "=l"(out) : "f"(lo), "f"(hi))
#define UNPACK2(lo, hi, in) asm("mov.b64 {%0, %1}, %2;" : "=f"(lo), "=f"(hi) : "l"(in))
#define ADD2(out, a, b)     asm("add.rn.f32x2 %0, %1, %2;" : "=l"(out) : "l"(a), "l"(b))
#define MUL2(out, a, b)     asm("mul.rn.f32x2 %0, %1, %2;" : "=l"(out) : "l"(a), "l"(b))

// ---------------- feature transpose (B,C,N) -> (B,N,C) -----------------------
__global__ void k_transpose(const float* __restrict__ f) {
    __shared__ float tile[32][33];
    int b = blockIdx.z, n0 = blockIdx.x*32, c0 = blockIdx.y*32;
    int tx = threadIdx.x, ty = threadIdx.y;
    for (int i = ty; i < 32; i += 8)
        tile[i][tx] = f[((size_t)b*CC + c0 + i)*NN + n0 + tx];
    __syncthreads();
    for (int i = ty; i < 32; i += 8)
        d_featT[((size_t)b*NN + n0 + i)*CC + c0 + tx] = tile[tx][i];
}

// ---------------- Morton counting sort: one CTA per batch --------------------
__global__ __launch_bounds__(1024,1) void k_sort(const float* __restrict__ xyz) {
    __shared__ int cnt[4096];
    __shared__ unsigned short cell[8192];
    __shared__ int wsum[32];
    int b = blockIdx.x, t = threadIdx.x;
    for (int i = t; i < 4096; i += 1024) cnt[i] = 0;
    __syncthreads();
    const float* xb = xyz + (size_t)b*NN*3;
    for (int i = t; i < NN; i += 1024) {
        float x = xb[i*3+0], y = xb[i*3+1], z = xb[i*3+2];
        int cx = min(15, max(0, (int)(x*16.0f)));
        int cy = min(15, max(0, (int)(y*16.0f)));
        int cz = min(15, max(0, (int)(z*16.0f)));
        int m = 0;
#pragma unroll
        for (int j = 0; j < 4; j++)
            m |= (((cx>>j)&1)<<(3*j)) | (((cy>>j)&1)<<(3*j+1)) | (((cz>>j)&1)<<(3*j+2));
        cell[i] = (unsigned short)m;
        atomicAdd(&cnt[m], 1);
    }
    __syncthreads();
    int c0 = cnt[t*4+0], c1 = cnt[t*4+1], c2 = cnt[t*4+2], c3 = cnt[t*4+3];
    int ts = c0+c1+c2+c3;
    int lane = t & 31, w = t >> 5;
    int x = ts;
#pragma unroll
    for (int o = 1; o < 32; o <<= 1) {
        int y = __shfl_up_sync(0xffffffffu, x, o);
        if (lane >= o) x += y;
    }
    if (lane == 31) wsum[w] = x;
    int wex = x - ts;
    __syncthreads();
    if (w == 0) {
        int v = wsum[lane];
        int xx = v;
#pragma unroll
        for (int o = 1; o < 32; o <<= 1) {
            int y = __shfl_up_sync(0xffffffffu, xx, o);
            if (lane >= o) xx += y;
        }
        wsum[lane] = xx - v;
    }
    __syncthreads();
    int basep = wsum[w] + wex;
    cnt[t*4+0] = basep;
    cnt[t*4+1] = basep + c0;
    cnt[t*4+2] = basep + c0 + c1;
    cnt[t*4+3] = basep + c0 + c1 + c2;
    __syncthreads();
    for (int i = t; i < NN; i += 1024) {
        int m = cell[i];
        int pos = atomicAdd(&cnt[m], 1);
        d_sx[b*NN+pos] = xb[i*3+0];
        d_sy[b*NN+pos] = xb[i*3+1];
        d_sz[b*NN+pos] = xb[i*3+2];
        d_sidx[b*NN+pos] = i;
    }
}

// ---------------- FPS: 1 CTA/batch, 1024 thr, 32 warps x 256 pts -------------
// Each warp owns 256 Morton-contiguous points (8/thread) with a bounding box
// and a cached (wmax,key). Skip the whole warp update iff
// dist2(center, box)*(1-1e-4) >= wmax — a provable bitwise no-op.
// One __syncthreads/iter; winner reduced redundantly per warp via 2x u32 REDUX
// over parity-double-buffered 32-slot (val,key) arrays.
__global__ __launch_bounds__(1024,1) void k_fps(const float* __restrict__ xyz,
                                                float* __restrict__ out_newxyz) {
    extern __shared__ float smem[];
    float* s_px = smem;              // 8192
    float* s_py = smem + 8192;
    float* s_pz = smem + 16384;
    __shared__ unsigned s_val[2][32];
    __shared__ unsigned s_key[2][32];

    const int b = blockIdx.x, tid = threadIdx.x;
    const int w = tid >> 5, lane = tid & 31;
    const int base = w*256 + lane*8;

    float X[8], Y[8], Z[8], dd[8];
    int OI[8];
    {
        const float* sx = d_sx + b*NN;
        const float* sy = d_sy + b*NN;
        const float* sz = d_sz + b*NN;
        const int*   si = d_sidx + b*NN;
#pragma unroll
        for (int q = 0; q < 2; q++) {
            float4 vx = *(const float4*)(sx + base + q*4);
            float4 vy = *(const float4*)(sy + base + q*4);
            float4 vz = *(const float4*)(sz + base + q*4);
            int4   vi = *(const int4*)  (si + base + q*4);
            X[q*4+0]=vx.x; X[q*4+1]=vx.y; X[q*4+2]=vx.z; X[q*4+3]=vx.w;
            Y[q*4+0]=vy.x; Y[q*4+1]=vy.y; Y[q*4+2]=vy.z; Y[q*4+3]=vy.w;
            Z[q*4+0]=vz.x; Z[q*4+1]=vz.y; Z[q*4+2]=vz.z; Z[q*4+3]=vz.w;
            OI[q*4+0]=vi.x; OI[q*4+1]=vi.y; OI[q*4+2]=vi.z; OI[q*4+3]=vi.w;
        }
#pragma unroll
        for (int i = 0; i < 8; i++) {
            s_px[base+i]=X[i]; s_py[base+i]=Y[i]; s_pz[base+i]=Z[i];
            dd[i]=1e10f;
        }
    }
    // warp bounding box
    float bxn=X[0],bxx=X[0],byn=Y[0],byx=Y[0],bzn=Z[0],bzx=Z[0];
#pragma unroll
    for (int i = 1; i < 8; i++) {
        bxn=fminf(bxn,X[i]); bxx=fmaxf(bxx,X[i]);
        byn=fminf(byn,Y[i]); byx=fmaxf(byx,Y[i]);
        bzn=fminf(bzn,Z[i]); bzx=fmaxf(bzx,Z[i]);
    }
#pragma unroll
    for (int o = 16; o >= 1; o >>= 1) {
        bxn=fminf(bxn,__shfl_xor_sync(0xffffffffu,bxn,o));
        bxx=fmaxf(bxx,__shfl_xor_sync(0xffffffffu,bxx,o));
        byn=fminf(byn,__shfl_xor_sync(0xffffffffu,byn,o));
        byx=fmaxf(byx,__shfl_xor_sync(0xffffffffu,byx,o));
        bzn=fminf(bzn,__shfl_xor_sync(0xffffffffu,bzn,o));
        bzx=fmaxf(bzx,__shfl_xor_sync(0xffffffffu,bzx,o));
    }
    // pack into f32x2 (X,Y,Z dead after this; regs reused)
    unsigned long long PX[4],PY[4],PZ[4];
#pragma unroll
    for (int j = 0; j < 4; j++) {
        PACK2(PX[j],X[2*j],X[2*j+1]);
        PACK2(PY[j],Y[2*j],Y[2*j+1]);
        PACK2(PZ[j],Z[2*j],Z[2*j+1]);
    }
    unsigned wmax = __float_as_uint(1e10f), wkey = 0xffffffffu;

    float lx, ly, lz;
    {
        const float* xb = xyz + (size_t)b*NN*3;
        lx = xb[0]; ly = xb[1]; lz = xb[2];
    }
    if (tid == 0) {
        float* o = out_newxyz + (size_t)b*NPOINT*3;
        o[0] = lx; o[1] = ly; o[2] = lz;
    }

    for (int it = 1; it < NPOINT; it++) {
        const int par = it & 1;
        // box lower bound (conservative, scaled down 1e-4)
        float dxl = fmaxf(fmaxf(__fadd_rn(bxn,-lx), __fadd_rn(lx,-bxx)), 0.0f);
        float dyl = fmaxf(fmaxf(__fadd_rn(byn,-ly), __fadd_rn(ly,-byx)), 0.0f);
        float dzl = fmaxf(fmaxf(__fadd_rn(bzn,-lz), __fadd_rn(lz,-bzx)), 0.0f);
        float dlb = (dxl*dxl + dyl*dyl + dzl*dzl) * 0.9999f;
        if (dlb < __uint_as_float(wmax)) {
            float nlx = -lx, nly = -ly, nlz = -lz;
            unsigned long long NLX, NLY, NLZ;
            PACK2(NLX,nlx,nlx); PACK2(NLY,nly,nly); PACK2(NLZ,nlz,nlz);
            float lv = 0.0f;
#pragma unroll
            for (int j = 0; j < 4; j++) {
                unsigned long long dx,dy,dz,qx,qy,qz,t,s;
                ADD2(dx,PX[j],NLX); ADD2(dy,PY[j],NLY); ADD2(dz,PZ[j],NLZ);
                MUL2(qx,dx,dx); MUL2(qy,dy,dy); MUL2(qz,dz,dz);
                ADD2(t,qx,qy); ADD2(s,t,qz);
                float da,db; UNPACK2(da,db,s);
                dd[2*j]   = fminf(dd[2*j],da);
                dd[2*j+1] = fminf(dd[2*j+1],db);
                lv = fmaxf(lv, fmaxf(dd[2*j], dd[2*j+1]));
            }
            wmax = __reduce_max_sync(0xffffffffu, __float_as_uint(lv));
            unsigned cand = 0xffffffffu;
            if (__float_as_uint(lv) == wmax) {
#pragma unroll
                for (int i = 0; i < 8; i++)
                    if (__float_as_uint(dd[i]) == wmax) {
                        unsigned k = ((unsigned)OI[i] << 13) | (unsigned)(base+i);
                        cand = min(cand, k);
                    }
            }
            wkey = __reduce_min_sync(0xffffffffu, cand);
        }
        if (lane == 0) { s_val[par][w] = wmax; s_key[par][w] = wkey; }
        __syncthreads();
        // redundant global reduce in every warp (32 slots == 32 lanes)
        unsigned v  = s_val[par][lane];
        unsigned m  = __reduce_max_sync(0xffffffffu, v);
        unsigned ck = (v == m) ? s_key[par][lane] : 0xffffffffu;
        unsigned gk = __reduce_min_sync(0xffffffffu, ck);
        int p = (int)(gk & 8191u);
        lx = s_px[p]; ly = s_py[p]; lz = s_pz[p];
        if (tid == 0) {
            float* o2 = out_newxyz + ((size_t)b*NPOINT + it)*3;
            o2[0] = lx; o2[1] = ly; o2[2] = lz;
        }
    }
}

// ---------------- ball query: smem-staged, 16 queries per 512-thr CTA --------
__global__ __launch_bounds__(512,2) void k_ballquery(const float* __restrict__ xyz,
                                                     const float* __restrict__ newxyz) {
    extern __shared__ float sm[];
    float* sx = sm;            // 8192
    float* sy = sm + 8192;
    float* sz = sm + 16384;
    int tid = threadIdx.x;
    int b = blockIdx.x >> 7;            // /128
    int qbase = (blockIdx.x & 127) * 16;

    const float4* src = (const float4*)(xyz + (size_t)b*NN*3);
    for (int i = tid; i < NN*3/4; i += 512) {
        float4 v = src[i];
        int e = 4*i;
#pragma unroll
        for (int k = 0; k < 4; k++) {
            float val = (k==0)?v.x:(k==1)?v.y:(k==2)?v.z:v.w;
            int e2 = e + k;
            int p = e2/3, c = e2 - p*3;
            if (c == 0) sx[p] = val; else if (c == 1) sy[p] = val; else sz[p] = val;
        }
    }
    __syncthreads();

    int w = tid >> 5, lane = tid & 31;
    int s = qbase + w;
    int gq = b*NPOINT + s;
    const float* np = newxyz + (size_t)gq*3;
    float qx = np[0], qy = np[1], qz = np[2];
    int* outp = d_ball_idx + (size_t)gq*NSAMPLE;

    int cnt = 0, firstIdx = 0; bool haveFirst = false;
    for (int j0 = 0; j0 < NN && cnt < NSAMPLE; j0 += 32) {
        int j = j0 + lane;
        float dx = __fadd_rn(sx[j], -qx);
        float dy = __fadd_rn(sy[j], -qy);
        float dz = __fadd_rn(sz[j], -qz);
        float d = __fadd_rn(__fadd_rn(__fmul_rn(dx,dx), __fmul_rn(dy,dy)),
                            __fmul_rn(dz,dz));
        bool in = d < RADIUS2;
        unsigned mm = __ballot_sync(0xffffffffu, in);
        if (mm) {
            if (!haveFirst) { firstIdx = j0 + __ffs(mm) - 1; haveFirst = true; }
            if (in) {
                int pos = cnt + __popc(mm & ((1u << lane) - 1u));
                if (pos < NSAMPLE) outp[pos] = j;
            }
            cnt += __popc(mm);
        }
    }
    int fs = cnt < NSAMPLE ? cnt : NSAMPLE;
    for (int pos = fs + lane; pos < NSAMPLE; pos += 32) outp[pos] = firstIdx;
}

// ---------------- layer 1: gather + GEMM(64x67) + stat partials --------------
__global__ __launch_bounds__(256,2) void k_layer1(const float* __restrict__ xyz,
                                                  const float* __restrict__ newxyz,
                                                  const float* __restrict__ W1) {
    extern __shared__ float sm[];
    float (*sg)[256] = (float(*)[256])sm;              // 67 x 256
    float (*sw)[64]  = (float(*)[64])(sm + 67*256);    // 67 x 64
    int tid = threadIdx.x;
    int pos0 = blockIdx.x * 256;

    for (int i = tid; i < 64*67; i += 256) { int o = i/67, c = i%67; sw[c][o] = W1[i]; }
    {
        int pos = pos0 + tid;
        int idx = d_ball_idx[pos];
        int b = pos >> 16;
        int s = (pos >> 5) & 2047;
        const float* nx = newxyz + ((size_t)b*NPOINT + s)*3;
        const float* pp = xyz + ((size_t)b*NN + idx)*3;
        sg[0][tid] = pp[0]-nx[0];
        sg[1][tid] = pp[1]-nx[1];
        sg[2][tid] = pp[2]-nx[2];
        const float4* fr = (const float4*)(d_featT + ((size_t)b*NN + idx)*CC);
#pragma unroll
        for (int c4 = 0; c4 < 16; c4++) {
            float4 v = fr[c4];
            sg[3+c4*4+0][tid] = v.x; sg[3+c4*4+1][tid] = v.y;
            sg[3+c4*4+2][tid] = v.z; sg[3+c4*4+3][tid] = v.w;
        }
    }
    __syncthreads();

    int tr = tid >> 5, tc = tid & 31;
    float acc[8][8];
#pragma unroll
    for (int i=0;i<8;i++)
#pragma unroll
        for (int j=0;j<8;j++) acc[i][j]=0.f;

#pragma unroll 2
    for (int k = 0; k < 67; k++) {
        float wv[8], g[8];
        *(float4*)&wv[0] = *(const float4*)&sw[k][tr*8];
        *(float4*)&wv[4] = *(const float4*)&sw[k][tr*8+4];
        *(float4*)&g[0] = *(const float4*)&sg[k][tc*8];
        *(float4*)&g[4] = *(const float4*)&sg[k][tc*8+4];
#pragma unroll
        for (int i=0;i<8;i++)
#pragma unroll
            for (int j=0;j<8;j++) acc[i][j] += wv[i]*g[j];
    }
#pragma unroll
    for (int i = 0; i < 8; i++) {
        int c = tr*8 + i;
        float* hp = d_h1 + (size_t)c*P_TOTAL + pos0 + tc*8;
        *(float4*)hp     = make_float4(acc[i][0],acc[i][1],acc[i][2],acc[i][3]);
        *(float4*)(hp+4) = make_float4(acc[i][4],acc[i][5],acc[i][6],acc[i][7]);
    }
#pragma unroll
    for (int i = 0; i < 8; i++) {
        float s = 0.f, q = 0.f;
#pragma unroll
        for (int j = 0; j < 8; j++) { s += acc[i][j]; q += acc[i][j]*acc[i][j]; }
#pragma unroll
        for (int o = 16; o > 0; o >>= 1) {
            s += __shfl_xor_sync(0xffffffffu, s, o);
            q += __shfl_xor_sync(0xffffffffu, q, o);
        }
        if (tc == 0) {
            int c = tr*8 + i;
            d_partials[((size_t)blockIdx.x*128 + c)*2 + 0] = s;
            d_partials[((size_t)blockIdx.x*128 + c)*2 + 1] = q;
        }
    }
}

// ---------------- deterministic stats reduce + BN fold -----------------------
__global__ void k_stats(const float* __restrict__ gam, const float* __restrict__ bet,
                        int nblocks) {
    int c = blockIdx.x, t = threadIdx.x;
    double s = 0.0, q = 0.0;
    for (int i = t; i < nblocks; i += 256) {
        s += (double)d_partials[((size_t)i*128 + c)*2 + 0];
        q += (double)d_partials[((size_t)i*128 + c)*2 + 1];
    }
    __shared__ double ss[256], qq[256];
    ss[t] = s; qq[t] = q; __syncthreads();
    for (int o = 128; o > 0; o >>= 1) {
        if (t < o) { ss[t] += ss[t+o]; qq[t] += qq[t+o]; }
        __syncthreads();
    }
    if (t == 0) {
        double mu  = ss[0] / (double)P_TOTAL;
        double var = qq[0] / (double)P_TOTAL - mu*mu;
        float a  = (float)((double)gam[c] / sqrt(var + 1e-5));
        float bp = (float)((double)bet[c] - mu * (double)a);
        d_ab[c*2] = a; d_ab[c*2+1] = bp;
    }
}

// ---------------- layer 2: bn1+relu on load, GEMM(64x64) ---------------------
__global__ __launch_bounds__(256,2) void k_layer2(const float* __restrict__ W2) {
    extern __shared__ float sm[];
    float (*sg)[256] = (float(*)[256])sm;              // 64 x 256
    float (*sw)[64]  = (float(*)[64])(sm + 64*256);    // 64 x 64
    int tid = threadIdx.x;
    int pos0 = blockIdx.x * 256;
    int wid = tid >> 5, lane = tid & 31;

    for (int i = tid; i < 64*64; i += 256) { int o = i/64, c = i%64; sw[c][o] = W2[i]; }
    for (int c = wid; c < 64; c += 8) {
        float a = d_ab[c*2], bp = d_ab[c*2+1];
        const float4* src = (const float4*)(d_h1 + (size_t)c*P_TOTAL + pos0) + lane*2;
        float4 v0 = src[0], v1 = src[1];
        v0.x=fmaxf(0.f,a*v0.x+bp); v0.y=fmaxf(0.f,a*v0.y+bp);
        v0.z=fmaxf(0.f,a*v0.z+bp); v0.w=fmaxf(0.f,a*v0.w+bp);
        v1.x=fmaxf(0.f,a*v1.x+bp); v1.y=fmaxf(0.f,a*v1.y+bp);
        v1.z=fmaxf(0.f,a*v1.z+bp); v1.w=fmaxf(0.f,a*v1.w+bp);
        *(float4*)&sg[c][lane*8]   = v0;
        *(float4*)&sg[c][lane*8+4] = v1;
    }
    __syncthreads();

    int tr = wid, tc = lane;
    float acc[8][8];
#pragma unroll
    for (int i=0;i<8;i++)
#pragma unroll
        for (int j=0;j<8;j++) acc[i][j]=0.f;
#pragma unroll 2
    for (int k = 0; k < 64; k++) {
        float wv[8], g[8];
        *(float4*)&wv[0] = *(const float4*)&sw[k][tr*8];
        *(float4*)&wv[4] = *(const float4*)&sw[k][tr*8+4];
        *(float4*)&g[0] = *(const float4*)&sg[k][tc*8];
        *(float4*)&g[4] = *(const float4*)&sg[k][tc*8+4];
#pragma unroll
        for (int i=0;i<8;i++)
#pragma unroll
            for (int j=0;j<8;j++) acc[i][j] += wv[i]*g[j];
    }
#pragma unroll
    for (int i = 0; i < 8; i++) {
        int c = tr*8 + i;
        float* hp = d_h2 + (size_t)c*P_TOTAL + pos0 + tc*8;
        *(float4*)hp     = make_float4(acc[i][0],acc[i][1],acc[i][2],acc[i][3]);
        *(float4*)(hp+4) = make_float4(acc[i][4],acc[i][5],acc[i][6],acc[i][7]);
    }
#pragma unroll
    for (int i = 0; i < 8; i++) {
        float s = 0.f, q = 0.f;
#pragma unroll
        for (int j = 0; j < 8; j++) { s += acc[i][j]; q += acc[i][j]*acc[i][j]; }
#pragma unroll
        for (int o = 16; o > 0; o >>= 1) {
            s += __shfl_xor_sync(0xffffffffu, s, o);
            q += __shfl_xor_sync(0xffffffffu, q, o);
        }
        if (tc == 0) {
            int c = tr*8 + i;
            d_partials[((size_t)blockIdx.x*128 + c)*2 + 0] = s;
            d_partials[((size_t)blockIdx.x*128 + c)*2 + 1] = q;
        }
    }
}

// ---------------- layer 3: bn2+relu on load, GEMM(128x64), fused max/min -----
__global__ __launch_bounds__(256,2) void k_layer3(const float* __restrict__ W3) {
    extern __shared__ float sm[];
    float (*sg)[128] = (float(*)[128])sm;              // 64 x 128
    float (*sw)[128] = (float(*)[128])(sm + 64*128);   // 64 x 128
    int tid = threadIdx.x;
    int pos0 = blockIdx.x * 128;
    int wid = tid >> 5, lane = tid & 31;

    for (int i = tid; i < 128*64; i += 256) { int o = i/64, c = i%64; sw[c][o] = W3[i]; }
    for (int c = wid; c < 64; c += 8) {
        float a = d_ab[c*2], bp = d_ab[c*2+1];
        const float4* src = (const float4*)(d_h2 + (size_t)c*P_TOTAL + pos0);
        float4 v = src[lane];
        v.x=fmaxf(0.f,a*v.x+bp); v.y=fmaxf(0.f,a*v.y+bp);
        v.z=fmaxf(0.f,a*v.z+bp); v.w=fmaxf(0.f,a*v.w+bp);
        *(float4*)&sg[c][lane*4] = v;
    }
    __syncthreads();

    int tr = tid >> 4, tc = tid & 15;
    float acc[8][8];
#pragma unroll
    for (int i=0;i<8;i++)
#pragma unroll
        for (int j=0;j<8;j++) acc[i][j]=0.f;
#pragma unroll 2
    for (int k = 0; k < 64; k++) {
        float wv[8], g[8];
        *(float4*)&wv[0] = *(const float4*)&sw[k][tr*8];
        *(float4*)&wv[4] = *(const float4*)&sw[k][tr*8+4];
        *(float4*)&g[0] = *(const float4*)&sg[k][tc*8];
        *(float4*)&g[4] = *(const float4*)&sg[k][tc*8+4];
#pragma unroll
        for (int i=0;i<8;i++)
#pragma unroll
            for (int j=0;j<8;j++) acc[i][j] += wv[i]*g[j];
    }
    int sglob = (pos0 >> 5) + (tc >> 2);
#pragma unroll
    for (int i = 0; i < 8; i++) {
        int c = tr*8 + i;
        float mx = acc[i][0], mn = acc[i][0];
#pragma unroll
        for (int j = 1; j < 8; j++) { mx = fmaxf(mx, acc[i][j]); mn = fminf(mn, acc[i][j]); }
        mx = fmaxf(mx, __shfl_xor_sync(0xffffffffu, mx, 1));
        mn = fminf(mn, __shfl_xor_sync(0xffffffffu, mn, 1));
        mx = fmaxf(mx, __shfl_xor_sync(0xffffffffu, mx, 2));
        mn = fminf(mn, __shfl_xor_sync(0xffffffffu, mn, 2));
        if ((tc & 3) == 0) {
            d_hmx[(size_t)c*(BB*NPOINT) + sglob] = mx;
            d_hmn[(size_t)c*(BB*NPOINT) + sglob] = mn;
        }
    }
#pragma unroll
    for (int i = 0; i < 8; i++) {
        float s = 0.f, q = 0.f;
#pragma unroll
        for (int j = 0; j < 8; j++) { s += acc[i][j]; q += acc[i][j]*acc[i][j]; }
#pragma unroll
        for (int o = 8; o > 0; o >>= 1) {
            s += __shfl_xor_sync(0xffffffffu, s, o);
            q += __shfl_xor_sync(0xffffffffu, q, o);
        }
        if (tc == 0) {
            int c = tr*8 + i;
            d_partials[((size_t)blockIdx.x*128 + c)*2 + 0] = s;
            d_partials[((size_t)blockIdx.x*128 + c)*2 + 1] = q;
        }
    }
}

// ---------------- bn3 + relu on the pooled extremum --------------------------
__global__ void k_finalize(float* __restrict__ feats) {
    int gid = blockIdx.x*blockDim.x + threadIdx.x;
    if (gid >= BB*128*NPOINT) return;
    int s = gid & 2047;
    int o = (gid >> 11) & 127;
    int b = gid >> 18;
    float a = d_ab[o*2], bp = d_ab[o*2+1];
    size_t ix = (size_t)o*(BB*NPOINT) + b*NPOINT + s;
    float v = (a >= 0.0f) ? d_hmx[ix] : d_hmn[ix];
    feats[gid] = fmaxf(0.0f, a*v + bp);
}

// ---------------- launch ------------------------------------------------------
extern "C" void kernel_launch(void* const* d_in, const int* in_sizes, int n_in,
                              void* d_out, int out_size) {
    const float* xyz      = (const float*)d_in[0];
    const float* features = (const float*)d_in[1];
    const float* W1 = (const float*)d_in[2];
    const float* g1 = (const float*)d_in[3];
    const float* b1 = (const float*)d_in[4];
    const float* W2 = (const float*)d_in[5];
    const float* g2 = (const float*)d_in[6];
    const float* b2 = (const float*)d_in[7];
    const float* W3 = (const float*)d_in[8];
    const float* g3 = (const float*)d_in[9];
    const float* b3 = (const float*)d_in[10];
    float* out    = (float*)d_out;
    float* newxyz = out;                       // 8*2048*3
    float* feats  = out + BB*NPOINT*3;         // 8*128*2048

    const int SMF = 3*NN*4;                    // 96KB: px,py,pz
    const int SMQ = 3*NN*4;                    // 96KB for ballquery stage
    const int SM1 = (67*256 + 67*64) * 4;
    const int SM2 = (64*256 + 64*64) * 4;
    const int SM3 = (64*128 + 64*128) * 4;
    cudaFuncSetAttribute(k_fps,       cudaFuncAttributeMaxDynamicSharedMemorySize, SMF);
    cudaFuncSetAttribute(k_ballquery, cudaFuncAttributeMaxDynamicSharedMemorySize, SMQ);
    cudaFuncSetAttribute(k_layer1,    cudaFuncAttributeMaxDynamicSharedMemorySize, SM1);
    cudaFuncSetAttribute(k_layer2,    cudaFuncAttributeMaxDynamicSharedMemorySize, SM2);
    cudaFuncSetAttribute(k_layer3,    cudaFuncAttributeMaxDynamicSharedMemorySize, SM3);

    k_transpose<<<dim3(NN/32, CC/32, BB), dim3(32,8)>>>(features);
    k_sort<<<BB, 1024>>>(xyz);
    k_fps<<<BB, 1024, SMF>>>(xyz, newxyz);
    k_ballquery<<<BB*128, 512, SMQ>>>(xyz, newxyz);

    k_layer1<<<P_TOTAL/256, 256, SM1>>>(xyz, newxyz, W1);
    k_stats<<<64, 256>>>(g1, b1, P_TOTAL/256);
    k_layer2<<<P_TOTAL/256, 256, SM2>>>(W2);
    k_stats<<<64, 256>>>(g2, b2, P_TOTAL/256);
    k_layer3<<<P_TOTAL/128, 256, SM3>>>(W3);
    k_stats<<<128, 256>>>(g3, b3, P_TOTAL/128);
    k_finalize<<<(BB*128*NPOINT)/256, 256>>>(feats);
}

// round 6
// speedup vs baseline: 2.8325x; 1.0109x over previous
#include <cuda_runtime.h>
#include <stdint.h>

#define BB 8
#define NN 8192
#define CC 64
#define NPOINT 2048
#define NSAMPLE 32
#define RADIUS2 0.04f
#define P_TOTAL (BB*NPOINT*NSAMPLE)   // 524288

// ---------------- scratch (device globals; no allocation allowed) ------------
__device__ float d_featT[BB*NN*CC];                 // 16.8 MB  (B,N,C)
__device__ int   d_ball_idx[P_TOTAL];
__device__ float d_h1[(size_t)64*P_TOTAL];          // 134 MB
__device__ float d_h2[(size_t)64*P_TOTAL];          // 134 MB
__device__ float d_hmx[(size_t)128*BB*NPOINT];      // 8 MB
__device__ float d_hmn[(size_t)128*BB*NPOINT];      // 8 MB
__device__ float d_partials[4096*128*2];            // 4 MB
__device__ float d_ab[128*2];                       // fused BN scale/shift
// Morton-sorted copies of xyz (+ original index)
__device__ float d_sx[BB*NN], d_sy[BB*NN], d_sz[BB*NN];
__device__ int   d_sidx[BB*NN];

// ---------------- packed f32x2 helpers (exact per-element RN) ----------------
#define PACK2(out, lo, hi)  asm("mov.b64 %0, {%1, %2};" : "=l"(out) : "f"(lo), "f"(hi))
#define UNPACK2(lo, hi, in) asm("mov.b64 {%0, %1}, %2;" : "=f"(lo), "=f"(hi) : "l"(in))
#define ADD2(out, a, b)     asm("add.rn.f32x2 %0, %1, %2;" : "=l"(out) : "l"(a), "l"(b))
#define MUL2(out, a, b)     asm("mul.rn.f32x2 %0, %1, %2;" : "=l"(out) : "l"(a), "l"(b))
#define FMA2(d, a, b, c)    asm("fma.rn.f32x2 %0, %1, %2, %3;" : "=l"(d) : "l"(a), "l"(b), "l"(c))

// ---------------- feature transpose (B,C,N) -> (B,N,C) -----------------------
__global__ void k_transpose(const float* __restrict__ f) {
    __shared__ float tile[32][33];
    int b = blockIdx.z, n0 = blockIdx.x*32, c0 = blockIdx.y*32;
    int tx = threadIdx.x, ty = threadIdx.y;
    for (int i = ty; i < 32; i += 8)
        tile[i][tx] = f[((size_t)b*CC + c0 + i)*NN + n0 + tx];
    __syncthreads();
    for (int i = ty; i < 32; i += 8)
        d_featT[((size_t)b*NN + n0 + i)*CC + c0 + tx] = tile[tx][i];
}

// ---------------- Morton counting sort: one CTA per batch --------------------
__global__ __launch_bounds__(1024,1) void k_sort(const float* __restrict__ xyz) {
    __shared__ int cnt[4096];
    __shared__ unsigned short cell[8192];
    __shared__ int wsum[32];
    int b = blockIdx.x, t = threadIdx.x;
    for (int i = t; i < 4096; i += 1024) cnt[i] = 0;
    __syncthreads();
    const float* xb = xyz + (size_t)b*NN*3;
    for (int i = t; i < NN; i += 1024) {
        float x = xb[i*3+0], y = xb[i*3+1], z = xb[i*3+2];
        int cx = min(15, max(0, (int)(x*16.0f)));
        int cy = min(15, max(0, (int)(y*16.0f)));
        int cz = min(15, max(0, (int)(z*16.0f)));
        int m = 0;
#pragma unroll
        for (int j = 0; j < 4; j++)
            m |= (((cx>>j)&1)<<(3*j)) | (((cy>>j)&1)<<(3*j+1)) | (((cz>>j)&1)<<(3*j+2));
        cell[i] = (unsigned short)m;
        atomicAdd(&cnt[m], 1);
    }
    __syncthreads();
    int c0 = cnt[t*4+0], c1 = cnt[t*4+1], c2 = cnt[t*4+2], c3 = cnt[t*4+3];
    int ts = c0+c1+c2+c3;
    int lane = t & 31, w = t >> 5;
    int x = ts;
#pragma unroll
    for (int o = 1; o < 32; o <<= 1) {
        int y = __shfl_up_sync(0xffffffffu, x, o);
        if (lane >= o) x += y;
    }
    if (lane == 31) wsum[w] = x;
    int wex = x - ts;
    __syncthreads();
    if (w == 0) {
        int v = wsum[lane];
        int xx = v;
#pragma unroll
        for (int o = 1; o < 32; o <<= 1) {
            int y = __shfl_up_sync(0xffffffffu, xx, o);
            if (lane >= o) xx += y;
        }
        wsum[lane] = xx - v;
    }
    __syncthreads();
    int basep = wsum[w] + wex;
    cnt[t*4+0] = basep;
    cnt[t*4+1] = basep + c0;
    cnt[t*4+2] = basep + c0 + c1;
    cnt[t*4+3] = basep + c0 + c1 + c2;
    __syncthreads();
    for (int i = t; i < NN; i += 1024) {
        int m = cell[i];
        int pos = atomicAdd(&cnt[m], 1);
        d_sx[b*NN+pos] = xb[i*3+0];
        d_sy[b*NN+pos] = xb[i*3+1];
        d_sz[b*NN+pos] = xb[i*3+2];
        d_sidx[b*NN+pos] = i;
    }
}

// ---------------- FPS: 1 CTA/batch, 1024 thr, 32 warps x 256 pts -------------
__global__ __launch_bounds__(1024,1) void k_fps(const float* __restrict__ xyz,
                                                float* __restrict__ out_newxyz) {
    extern __shared__ float smem[];
    float* s_px = smem;              // 8192
    float* s_py = smem + 8192;
    float* s_pz = smem + 16384;
    __shared__ unsigned s_val[2][32];
    __shared__ unsigned s_key[2][32];

    const int b = blockIdx.x, tid = threadIdx.x;
    const int w = tid >> 5, lane = tid & 31;
    const int base = w*256 + lane*8;

    float X[8], Y[8], Z[8], dd[8];
    int OI[8];
    {
        const float* sx = d_sx + b*NN;
        const float* sy = d_sy + b*NN;
        const float* sz = d_sz + b*NN;
        const int*   si = d_sidx + b*NN;
#pragma unroll
        for (int q = 0; q < 2; q++) {
            float4 vx = *(const float4*)(sx + base + q*4);
            float4 vy = *(const float4*)(sy + base + q*4);
            float4 vz = *(const float4*)(sz + base + q*4);
            int4   vi = *(const int4*)  (si + base + q*4);
            X[q*4+0]=vx.x; X[q*4+1]=vx.y; X[q*4+2]=vx.z; X[q*4+3]=vx.w;
            Y[q*4+0]=vy.x; Y[q*4+1]=vy.y; Y[q*4+2]=vy.z; Y[q*4+3]=vy.w;
            Z[q*4+0]=vz.x; Z[q*4+1]=vz.y; Z[q*4+2]=vz.z; Z[q*4+3]=vz.w;
            OI[q*4+0]=vi.x; OI[q*4+1]=vi.y; OI[q*4+2]=vi.z; OI[q*4+3]=vi.w;
        }
#pragma unroll
        for (int i = 0; i < 8; i++) {
            s_px[base+i]=X[i]; s_py[base+i]=Y[i]; s_pz[base+i]=Z[i];
            dd[i]=1e10f;
        }
    }
    float bxn=X[0],bxx=X[0],byn=Y[0],byx=Y[0],bzn=Z[0],bzx=Z[0];
#pragma unroll
    for (int i = 1; i < 8; i++) {
        bxn=fminf(bxn,X[i]); bxx=fmaxf(bxx,X[i]);
        byn=fminf(byn,Y[i]); byx=fmaxf(byx,Y[i]);
        bzn=fminf(bzn,Z[i]); bzx=fmaxf(bzx,Z[i]);
    }
#pragma unroll
    for (int o = 16; o >= 1; o >>= 1) {
        bxn=fminf(bxn,__shfl_xor_sync(0xffffffffu,bxn,o));
        bxx=fmaxf(bxx,__shfl_xor_sync(0xffffffffu,bxx,o));
        byn=fminf(byn,__shfl_xor_sync(0xffffffffu,byn,o));
        byx=fmaxf(byx,__shfl_xor_sync(0xffffffffu,byx,o));
        bzn=fminf(bzn,__shfl_xor_sync(0xffffffffu,bzn,o));
        bzx=fmaxf(bzx,__shfl_xor_sync(0xffffffffu,bzx,o));
    }
    unsigned long long PX[4],PY[4],PZ[4];
#pragma unroll
    for (int j = 0; j < 4; j++) {
        PACK2(PX[j],X[2*j],X[2*j+1]);
        PACK2(PY[j],Y[2*j],Y[2*j+1]);
        PACK2(PZ[j],Z[2*j],Z[2*j+1]);
    }
    unsigned wmax = __float_as_uint(1e10f), wkey = 0xffffffffu;

    float lx, ly, lz;
    {
        const float* xb = xyz + (size_t)b*NN*3;
        lx = xb[0]; ly = xb[1]; lz = xb[2];
    }
    if (tid == 0) {
        float* o = out_newxyz + (size_t)b*NPOINT*3;
        o[0] = lx; o[1] = ly; o[2] = lz;
    }

    for (int it = 1; it < NPOINT; it++) {
        const int par = it & 1;
        float dxl = fmaxf(fmaxf(__fadd_rn(bxn,-lx), __fadd_rn(lx,-bxx)), 0.0f);
        float dyl = fmaxf(fmaxf(__fadd_rn(byn,-ly), __fadd_rn(ly,-byx)), 0.0f);
        float dzl = fmaxf(fmaxf(__fadd_rn(bzn,-lz), __fadd_rn(lz,-bzx)), 0.0f);
        float dlb = (dxl*dxl + dyl*dyl + dzl*dzl) * 0.9999f;
        if (dlb < __uint_as_float(wmax)) {
            float nlx = -lx, nly = -ly, nlz = -lz;
            unsigned long long NLX, NLY, NLZ;
            PACK2(NLX,nlx,nlx); PACK2(NLY,nly,nly); PACK2(NLZ,nlz,nlz);
            float lv = 0.0f;
#pragma unroll
            for (int j = 0; j < 4; j++) {
                unsigned long long dx,dy,dz,qx,qy,qz,t,s;
                ADD2(dx,PX[j],NLX); ADD2(dy,PY[j],NLY); ADD2(dz,PZ[j],NLZ);
                MUL2(qx,dx,dx); MUL2(qy,dy,dy); MUL2(qz,dz,dz);
                ADD2(t,qx,qy); ADD2(s,t,qz);
                float da,db; UNPACK2(da,db,s);
                dd[2*j]   = fminf(dd[2*j],da);
                dd[2*j+1] = fminf(dd[2*j+1],db);
                lv = fmaxf(lv, fmaxf(dd[2*j], dd[2*j+1]));
            }
            wmax = __reduce_max_sync(0xffffffffu, __float_as_uint(lv));
            unsigned cand = 0xffffffffu;
            if (__float_as_uint(lv) == wmax) {
#pragma unroll
                for (int i = 0; i < 8; i++)
                    if (__float_as_uint(dd[i]) == wmax) {
                        unsigned k = ((unsigned)OI[i] << 13) | (unsigned)(base+i);
                        cand = min(cand, k);
                    }
            }
            wkey = __reduce_min_sync(0xffffffffu, cand);
        }
        if (lane == 0) { s_val[par][w] = wmax; s_key[par][w] = wkey; }
        __syncthreads();
        unsigned v  = s_val[par][lane];
        unsigned m  = __reduce_max_sync(0xffffffffu, v);
        unsigned ck = (v == m) ? s_key[par][lane] : 0xffffffffu;
        unsigned gk = __reduce_min_sync(0xffffffffu, ck);
        int p = (int)(gk & 8191u);
        lx = s_px[p]; ly = s_py[p]; lz = s_pz[p];
        if (tid == 0) {
            float* o2 = out_newxyz + ((size_t)b*NPOINT + it)*3;
            o2[0] = lx; o2[1] = ly; o2[2] = lz;
        }
    }
}

// ---------------- ball query: smem-staged, 16 queries per 512-thr CTA --------
__global__ __launch_bounds__(512,2) void k_ballquery(const float* __restrict__ xyz,
                                                     const float* __restrict__ newxyz) {
    extern __shared__ float sm[];
    float* sx = sm;
    float* sy = sm + 8192;
    float* sz = sm + 16384;
    int tid = threadIdx.x;
    int b = blockIdx.x >> 7;
    int qbase = (blockIdx.x & 127) * 16;

    const float4* src = (const float4*)(xyz + (size_t)b*NN*3);
    for (int i = tid; i < NN*3/4; i += 512) {
        float4 v = src[i];
        int e = 4*i;
#pragma unroll
        for (int k = 0; k < 4; k++) {
            float val = (k==0)?v.x:(k==1)?v.y:(k==2)?v.z:v.w;
            int e2 = e + k;
            int p = e2/3, c = e2 - p*3;
            if (c == 0) sx[p] = val; else if (c == 1) sy[p] = val; else sz[p] = val;
        }
    }
    __syncthreads();

    int w = tid >> 5, lane = tid & 31;
    int s = qbase + w;
    int gq = b*NPOINT + s;
    const float* np = newxyz + (size_t)gq*3;
    float qx = np[0], qy = np[1], qz = np[2];
    int* outp = d_ball_idx + (size_t)gq*NSAMPLE;

    int cnt = 0, firstIdx = 0; bool haveFirst = false;
    for (int j0 = 0; j0 < NN && cnt < NSAMPLE; j0 += 32) {
        int j = j0 + lane;
        float dx = __fadd_rn(sx[j], -qx);
        float dy = __fadd_rn(sy[j], -qy);
        float dz = __fadd_rn(sz[j], -qz);
        float d = __fadd_rn(__fadd_rn(__fmul_rn(dx,dx), __fmul_rn(dy,dy)),
                            __fmul_rn(dz,dz));
        bool in = d < RADIUS2;
        unsigned mm = __ballot_sync(0xffffffffu, in);
        if (mm) {
            if (!haveFirst) { firstIdx = j0 + __ffs(mm) - 1; haveFirst = true; }
            if (in) {
                int pos = cnt + __popc(mm & ((1u << lane) - 1u));
                if (pos < NSAMPLE) outp[pos] = j;
            }
            cnt += __popc(mm);
        }
    }
    int fs = cnt < NSAMPLE ? cnt : NSAMPLE;
    for (int pos = fs + lane; pos < NSAMPLE; pos += 32) outp[pos] = firstIdx;
}

// ======== packed-FMA 8x8 micro-kernel body (shared by the 3 layers) ==========
// acc2[i][jp] accumulates the (i, 2jp / 2jp+1) outputs via fma.rn.f32x2.
#define MM8x8_K(sw_row, sg_row)                                               \
    do {                                                                      \
        float wv[8], g[8];                                                    \
        *(float4*)&wv[0] = *(const float4*)&(sw_row)[0];                      \
        *(float4*)&wv[4] = *(const float4*)&(sw_row)[4];                      \
        *(float4*)&g[0]  = *(const float4*)&(sg_row)[0];                      \
        *(float4*)&g[4]  = *(const float4*)&(sg_row)[4];                      \
        unsigned long long g2[4];                                             \
        PACK2(g2[0], g[0], g[1]); PACK2(g2[1], g[2], g[3]);                   \
        PACK2(g2[2], g[4], g[5]); PACK2(g2[3], g[6], g[7]);                   \
        _Pragma("unroll")                                                     \
        for (int i = 0; i < 8; i++) {                                         \
            unsigned long long w2; PACK2(w2, wv[i], wv[i]);                   \
            FMA2(acc2[i][0], w2, g2[0], acc2[i][0]);                          \
            FMA2(acc2[i][1], w2, g2[1], acc2[i][1]);                          \
            FMA2(acc2[i][2], w2, g2[2], acc2[i][2]);                          \
            FMA2(acc2[i][3], w2, g2[3], acc2[i][3]);                          \
        }                                                                     \
    } while (0)

// ---------------- layer 1: gather + GEMM(64x67) + stat partials --------------
__global__ __launch_bounds__(256,2) void k_layer1(const float* __restrict__ xyz,
                                                  const float* __restrict__ newxyz,
                                                  const float* __restrict__ W1) {
    extern __shared__ float sm[];
    float (*sg)[256] = (float(*)[256])sm;              // 67 x 256
    float (*sw)[64]  = (float(*)[64])(sm + 67*256);    // 67 x 64
    int tid = threadIdx.x;
    int pos0 = blockIdx.x * 256;

    for (int i = tid; i < 64*67; i += 256) { int o = i/67, c = i%67; sw[c][o] = W1[i]; }
    {
        int pos = pos0 + tid;
        int idx = d_ball_idx[pos];
        int b = pos >> 16;
        int s = (pos >> 5) & 2047;
        const float* nx = newxyz + ((size_t)b*NPOINT + s)*3;
        const float* pp = xyz + ((size_t)b*NN + idx)*3;
        sg[0][tid] = pp[0]-nx[0];
        sg[1][tid] = pp[1]-nx[1];
        sg[2][tid] = pp[2]-nx[2];
        const float4* fr = (const float4*)(d_featT + ((size_t)b*NN + idx)*CC);
#pragma unroll
        for (int c4 = 0; c4 < 16; c4++) {
            float4 v = fr[c4];
            sg[3+c4*4+0][tid] = v.x; sg[3+c4*4+1][tid] = v.y;
            sg[3+c4*4+2][tid] = v.z; sg[3+c4*4+3][tid] = v.w;
        }
    }
    __syncthreads();

    int tr = tid >> 5, tc = tid & 31;
    unsigned long long acc2[8][4];
#pragma unroll
    for (int i=0;i<8;i++)
#pragma unroll
        for (int j=0;j<4;j++) acc2[i][j]=0ull;

#pragma unroll 2
    for (int k = 0; k < 67; k++)
        MM8x8_K(&sw[k][tr*8], &sg[k][tc*8]);

    float acc[8][8];
#pragma unroll
    for (int i=0;i<8;i++)
#pragma unroll
        for (int j=0;j<4;j++) UNPACK2(acc[i][2*j], acc[i][2*j+1], acc2[i][j]);

#pragma unroll
    for (int i = 0; i < 8; i++) {
        int c = tr*8 + i;
        float* hp = d_h1 + (size_t)c*P_TOTAL + pos0 + tc*8;
        *(float4*)hp     = make_float4(acc[i][0],acc[i][1],acc[i][2],acc[i][3]);
        *(float4*)(hp+4) = make_float4(acc[i][4],acc[i][5],acc[i][6],acc[i][7]);
    }
#pragma unroll
    for (int i = 0; i < 8; i++) {
        float s = 0.f, q = 0.f;
#pragma unroll
        for (int j = 0; j < 8; j++) { s += acc[i][j]; q += acc[i][j]*acc[i][j]; }
#pragma unroll
        for (int o = 16; o > 0; o >>= 1) {
            s += __shfl_xor_sync(0xffffffffu, s, o);
            q += __shfl_xor_sync(0xffffffffu, q, o);
        }
        if (tc == 0) {
            int c = tr*8 + i;
            d_partials[((size_t)blockIdx.x*128 + c)*2 + 0] = s;
            d_partials[((size_t)blockIdx.x*128 + c)*2 + 1] = q;
        }
    }
}

// ---------------- deterministic stats reduce + BN fold -----------------------
__global__ void k_stats(const float* __restrict__ gam, const float* __restrict__ bet,
                        int nblocks) {
    int c = blockIdx.x, t = threadIdx.x;
    double s = 0.0, q = 0.0;
    for (int i = t; i < nblocks; i += 256) {
        s += (double)d_partials[((size_t)i*128 + c)*2 + 0];
        q += (double)d_partials[((size_t)i*128 + c)*2 + 1];
    }
    __shared__ double ss[256], qq[256];
    ss[t] = s; qq[t] = q; __syncthreads();
    for (int o = 128; o > 0; o >>= 1) {
        if (t < o) { ss[t] += ss[t+o]; qq[t] += qq[t+o]; }
        __syncthreads();
    }
    if (t == 0) {
        double mu  = ss[0] / (double)P_TOTAL;
        double var = qq[0] / (double)P_TOTAL - mu*mu;
        float a  = (float)((double)gam[c] / sqrt(var + 1e-5));
        float bp = (float)((double)bet[c] - mu * (double)a);
        d_ab[c*2] = a; d_ab[c*2+1] = bp;
    }
}

// ---------------- layer 2: bn1+relu on load, GEMM(64x64) ---------------------
__global__ __launch_bounds__(256,2) void k_layer2(const float* __restrict__ W2) {
    extern __shared__ float sm[];
    float (*sg)[256] = (float(*)[256])sm;              // 64 x 256
    float (*sw)[64]  = (float(*)[64])(sm + 64*256);    // 64 x 64
    int tid = threadIdx.x;
    int pos0 = blockIdx.x * 256;
    int wid = tid >> 5, lane = tid & 31;

    for (int i = tid; i < 64*64; i += 256) { int o = i/64, c = i%64; sw[c][o] = W2[i]; }
    for (int c = wid; c < 64; c += 8) {
        float a = d_ab[c*2], bp = d_ab[c*2+1];
        const float4* src = (const float4*)(d_h1 + (size_t)c*P_TOTAL + pos0) + lane*2;
        float4 v0 = src[0], v1 = src[1];
        v0.x=fmaxf(0.f,a*v0.x+bp); v0.y=fmaxf(0.f,a*v0.y+bp);
        v0.z=fmaxf(0.f,a*v0.z+bp); v0.w=fmaxf(0.f,a*v0.w+bp);
        v1.x=fmaxf(0.f,a*v1.x+bp); v1.y=fmaxf(0.f,a*v1.y+bp);
        v1.z=fmaxf(0.f,a*v1.z+bp); v1.w=fmaxf(0.f,a*v1.w+bp);
        *(float4*)&sg[c][lane*8]   = v0;
        *(float4*)&sg[c][lane*8+4] = v1;
    }
    __syncthreads();

    int tr = wid, tc = lane;
    unsigned long long acc2[8][4];
#pragma unroll
    for (int i=0;i<8;i++)
#pragma unroll
        for (int j=0;j<4;j++) acc2[i][j]=0ull;

#pragma unroll 2
    for (int k = 0; k < 64; k++)
        MM8x8_K(&sw[k][tr*8], &sg[k][tc*8]);

    float acc[8][8];
#pragma unroll
    for (int i=0;i<8;i++)
#pragma unroll
        for (int j=0;j<4;j++) UNPACK2(acc[i][2*j], acc[i][2*j+1], acc2[i][j]);

#pragma unroll
    for (int i = 0; i < 8; i++) {
        int c = tr*8 + i;
        float* hp = d_h2 + (size_t)c*P_TOTAL + pos0 + tc*8;
        *(float4*)hp     = make_float4(acc[i][0],acc[i][1],acc[i][2],acc[i][3]);
        *(float4*)(hp+4) = make_float4(acc[i][4],acc[i][5],acc[i][6],acc[i][7]);
    }
#pragma unroll
    for (int i = 0; i < 8; i++) {
        float s = 0.f, q = 0.f;
#pragma unroll
        for (int j = 0; j < 8; j++) { s += acc[i][j]; q += acc[i][j]*acc[i][j]; }
#pragma unroll
        for (int o = 16; o > 0; o >>= 1) {
            s += __shfl_xor_sync(0xffffffffu, s, o);
            q += __shfl_xor_sync(0xffffffffu, q, o);
        }
        if (tc == 0) {
            int c = tr*8 + i;
            d_partials[((size_t)blockIdx.x*128 + c)*2 + 0] = s;
            d_partials[((size_t)blockIdx.x*128 + c)*2 + 1] = q;
        }
    }
}

// ---------------- layer 3: bn2+relu on load, GEMM(128x64), fused max/min -----
__global__ __launch_bounds__(256,2) void k_layer3(const float* __restrict__ W3) {
    extern __shared__ float sm[];
    float (*sg)[128] = (float(*)[128])sm;              // 64 x 128
    float (*sw)[128] = (float(*)[128])(sm + 64*128);   // 64 x 128
    int tid = threadIdx.x;
    int pos0 = blockIdx.x * 128;
    int wid = tid >> 5, lane = tid & 31;

    for (int i = tid; i < 128*64; i += 256) { int o = i/64, c = i%64; sw[c][o] = W3[i]; }
    for (int c = wid; c < 64; c += 8) {
        float a = d_ab[c*2], bp = d_ab[c*2+1];
        const float4* src = (const float4*)(d_h2 + (size_t)c*P_TOTAL + pos0);
        float4 v = src[lane];
        v.x=fmaxf(0.f,a*v.x+bp); v.y=fmaxf(0.f,a*v.y+bp);
        v.z=fmaxf(0.f,a*v.z+bp); v.w=fmaxf(0.f,a*v.w+bp);
        *(float4*)&sg[c][lane*4] = v;
    }
    __syncthreads();

    int tr = tid >> 4, tc = tid & 15;
    unsigned long long acc2[8][4];
#pragma unroll
    for (int i=0;i<8;i++)
#pragma unroll
        for (int j=0;j<4;j++) acc2[i][j]=0ull;

#pragma unroll 2
    for (int k = 0; k < 64; k++)
        MM8x8_K(&sw[k][tr*8], &sg[k][tc*8]);

    float acc[8][8];
#pragma unroll
    for (int i=0;i<8;i++)
#pragma unroll
        for (int j=0;j<4;j++) UNPACK2(acc[i][2*j], acc[i][2*j+1], acc2[i][j]);

    int sglob = (pos0 >> 5) + (tc >> 2);
#pragma unroll
    for (int i = 0; i < 8; i++) {
        int c = tr*8 + i;
        float mx = acc[i][0], mn = acc[i][0];
#pragma unroll
        for (int j = 1; j < 8; j++) { mx = fmaxf(mx, acc[i][j]); mn = fminf(mn, acc[i][j]); }
        mx = fmaxf(mx, __shfl_xor_sync(0xffffffffu, mx, 1));
        mn = fminf(mn, __shfl_xor_sync(0xffffffffu, mn, 1));
        mx = fmaxf(mx, __shfl_xor_sync(0xffffffffu, mx, 2));
        mn = fminf(mn, __shfl_xor_sync(0xffffffffu, mn, 2));
        if ((tc & 3) == 0) {
            d_hmx[(size_t)c*(BB*NPOINT) + sglob] = mx;
            d_hmn[(size_t)c*(BB*NPOINT) + sglob] = mn;
        }
    }
#pragma unroll
    for (int i = 0; i < 8; i++) {
        float s = 0.f, q = 0.f;
#pragma unroll
        for (int j = 0; j < 8; j++) { s += acc[i][j]; q += acc[i][j]*acc[i][j]; }
#pragma unroll
        for (int o = 8; o > 0; o >>= 1) {
            s += __shfl_xor_sync(0xffffffffu, s, o);
            q += __shfl_xor_sync(0xffffffffu, q, o);
        }
        if (tc == 0) {
            int c = tr*8 + i;
            d_partials[((size_t)blockIdx.x*128 + c)*2 + 0] = s;
            d_partials[((size_t)blockIdx.x*128 + c)*2 + 1] = q;
        }
    }
}

// ---------------- bn3 + relu on the pooled extremum --------------------------
__global__ void k_finalize(float* __restrict__ feats) {
    int gid = blockIdx.x*blockDim.x + threadIdx.x;
    if (gid >= BB*128*NPOINT) return;
    int s = gid & 2047;
    int o = (gid >> 11) & 127;
    int b = gid >> 18;
    float a = d_ab[o*2], bp = d_ab[o*2+1];
    size_t ix = (size_t)o*(BB*NPOINT) + b*NPOINT + s;
    float v = (a >= 0.0f) ? d_hmx[ix] : d_hmn[ix];
    feats[gid] = fmaxf(0.0f, a*v + bp);
}

// ---------------- launch ------------------------------------------------------
extern "C" void kernel_launch(void* const* d_in, const int* in_sizes, int n_in,
                              void* d_out, int out_size) {
    const float* xyz      = (const float*)d_in[0];
    const float* features = (const float*)d_in[1];
    const float* W1 = (const float*)d_in[2];
    const float* g1 = (const float*)d_in[3];
    const float* b1 = (const float*)d_in[4];
    const float* W2 = (const float*)d_in[5];
    const float* g2 = (const float*)d_in[6];
    const float* b2 = (const float*)d_in[7];
    const float* W3 = (const float*)d_in[8];
    const float* g3 = (const float*)d_in[9];
    const float* b3 = (const float*)d_in[10];
    float* out    = (float*)d_out;
    float* newxyz = out;                       // 8*2048*3
    float* feats  = out + BB*NPOINT*3;         // 8*128*2048

    const int SMF = 3*NN*4;
    const int SMQ = 3*NN*4;
    const int SM1 = (67*256 + 67*64) * 4;
    const int SM2 = (64*256 + 64*64) * 4;
    const int SM3 = (64*128 + 64*128) * 4;
    cudaFuncSetAttribute(k_fps,       cudaFuncAttributeMaxDynamicSharedMemorySize, SMF);
    cudaFuncSetAttribute(k_ballquery, cudaFuncAttributeMaxDynamicSharedMemorySize, SMQ);
    cudaFuncSetAttribute(k_layer1,    cudaFuncAttributeMaxDynamicSharedMemorySize, SM1);
    cudaFuncSetAttribute(k_layer2,    cudaFuncAttributeMaxDynamicSharedMemorySize, SM2);
    cudaFuncSetAttribute(k_layer3,    cudaFuncAttributeMaxDynamicSharedMemorySize, SM3);

    k_transpose<<<dim3(NN/32, CC/32, BB), dim3(32,8)>>>(features);
    k_sort<<<BB, 1024>>>(xyz);
    k_fps<<<BB, 1024, SMF>>>(xyz, newxyz);
    k_ballquery<<<BB*128, 512, SMQ>>>(xyz, newxyz);

    k_layer1<<<P_TOTAL/256, 256, SM1>>>(xyz, newxyz, W1);
    k_stats<<<64, 256>>>(g1, b1, P_TOTAL/256);
    k_layer2<<<P_TOTAL/256, 256, SM2>>>(W2);
    k_stats<<<64, 256>>>(g2, b2, P_TOTAL/256);
    k_layer3<<<P_TOTAL/128, 256, SM3>>>(W3);
    k_stats<<<128, 256>>>(g3, b3, P_TOTAL/128);
    k_finalize<<<(BB*128*NPOINT)/256, 256>>>(feats);
}